// round 14
// baseline (speedup 1.0000x reference)
#include <cuda_runtime.h>
#include <cuda_bf16.h>

#define NB 256
#define NT 96
#define ND 32
#define NOUT 32
#define NH 128
#define NF 24
#define BC 64
#define NCTA 128
#define NTHR 512
#define GST 130

#define F_CNT (NB*NF*NOUT)
#define A_OFS F_CNT
#define A_CNT (NB*NT*ND)
#define B_OFS (A_OFS + A_CNT)
#define O_OFS (B_OFS + NB*NF*ND)

typedef unsigned long long ull;

__device__ float g_h[ND*NB*NH];
__device__ float g_c[ND*NB*NH];
__device__ float g_den[NB*ND];
__device__ float g_mug[NB*ND*NOUT];
__device__ float g_btg[NB*ND];
__device__ float g_mu2[2][NB*ND*NOUT];
__device__ float g_bt2[2][NB*ND];
__device__ unsigned g_cnt;
__device__ unsigned g_gen;
__device__ __nv_bfloat16 g_Wimg[4*32*32768];  // [gate][d][hi 16384 | lo 16384], swizzled

// ---- helpers ----
__device__ __forceinline__ float sigf(float x) { return __fdividef(1.f, 1.f + __expf(-x)); }
__device__ __forceinline__ float tanhfast(float x) {
    float e = __expf(-2.f * x);
    return __fdividef(1.f - e, 1.f + e);
}
__device__ __forceinline__ void cp16(unsigned dst, const void* src) {
    asm volatile("cp.async.cg.shared.global [%0], [%1], 16;" :: "r"(dst), "l"(src));
}
__device__ __forceinline__ void cp_commit() { asm volatile("cp.async.commit_group;"); }
template<int N> __device__ __forceinline__ void cp_wait() {
    asm volatile("cp.async.wait_group %0;" :: "n"(N));
}
__device__ __forceinline__ unsigned sptr(const void* p) {
    return (unsigned)__cvta_generic_to_shared(p);
}
#define LDX4(r, a) asm volatile("ldmatrix.sync.aligned.m8n8.x4.shared.b16 {%0,%1,%2,%3},[%4];" \
    : "=r"((r)[0]),"=r"((r)[1]),"=r"((r)[2]),"=r"((r)[3]) : "r"(a))
#define MMA(dd, a, b0v, b1v) asm volatile( \
    "mma.sync.aligned.m16n8k16.row.col.f32.bf16.bf16.f32 {%0,%1,%2,%3},{%4,%5,%6,%7},{%8,%9},{%0,%1,%2,%3};" \
    : "+f"((dd)[0]),"+f"((dd)[1]),"+f"((dd)[2]),"+f"((dd)[3]) \
    : "r"((a)[0]),"r"((a)[1]),"r"((a)[2]),"r"((a)[3]),"r"(b0v),"r"(b1v))

__device__ __forceinline__ void splitbf(float a, float b, unsigned &hi, unsigned &lo) {
    __nv_bfloat16 ah = __float2bfloat16(a), bh = __float2bfloat16(b);
    __nv_bfloat16 al2 = __float2bfloat16(a - __bfloat162float(ah));
    __nv_bfloat16 bl2 = __float2bfloat16(b - __bfloat162float(bh));
    hi = (unsigned)*(unsigned short*)&ah | ((unsigned)*(unsigned short*)&bh << 16);
    lo = (unsigned)*(unsigned short*)&al2 | ((unsigned)*(unsigned short*)&bl2 << 16);
}

// ==== prep: W^T bf16 hi/lo swizzled images ====
__global__ void prep_kernel(const float* __restrict__ Wj, const float* __restrict__ Wi,
                            const float* __restrict__ Wf, const float* __restrict__ Wo) {
    int idx = blockIdx.x*256 + threadIdx.x;
    if (idx >= 4*32*128*64) return;
    int i2 = idx & 63, n = (idx>>6)&127, dd = (idx>>13)&31, g = idx>>18;
    const float* W = (g==0?Wj:g==1?Wi:g==2?Wf:Wo) + (size_t)dd*NH*NH;
    int k = 2*i2;
    float w0 = W[k*NH + n], w1 = W[(k+1)*NH + n];
    unsigned hv, lv;
    splitbf(w0, w1, hv, lv);
    unsigned off = (unsigned)(n*128 + (((k>>3) ^ (n&7))<<3) + (k&7));
    __nv_bfloat16* base = g_Wimg + ((size_t)g*32 + dd)*32768;
    *(unsigned*)((char*)base + off*2)         = hv;
    *(unsigned*)((char*)base + 32768 + off*2) = lv;
}

// ---- shared W copy (64KB gate image into buf gi&1) ----
__device__ __forceinline__ void copyW2(unsigned wB, int d, int gi, int tid) {
    const char* src = (const char*)(g_Wimg + ((size_t)gi*32 + d)*32768) + tid*16;
    unsigned dst = wB + (unsigned)(gi & 1)*65536u + (unsigned)tid*16u;
#pragma unroll
    for (int j = 0; j < 8; ++j) cp16(dst + j*8192u, src + j*8192);
    cp_commit();
}

// ---- shared HMMA LSTM cell (proven R13 body) ----
// precondition: copy for gate0 issued. postcondition (!lastcell): next gate0 issued.
__device__ __forceinline__ void cell_hmma(
    unsigned wB, unsigned aHiB, unsigned aLoB,
    const float* __restrict__ ub, const float* __restrict__ xs,
    int d, int tid, int lane, int w,
    float* c, float* h2, bool lastcell)
{
    const int rg = w & 3, gq = w >> 2;
    const int t4 = lane & 3;
    const int R = rg*16 + (lane >> 2);
    const int l8 = lane & 7, m = lane >> 3;
    const int rowA = rg*16 + ((m & 1) << 3) + l8; const int jA = (m >> 1) & 1;
    const int rowB0 = gq*32 + ((m >> 1) << 3) + l8; const int jB = m & 1;
    const int rowB1 = rowB0 + 16;

#pragma unroll
    for (int g = 0; g < 4; ++g) {
        bool more = (g < 3) || !lastcell;
        if (more) copyW2(wB, d, (g + 1) & 3, tid);
        if (more) cp_wait<1>(); else cp_wait<0>();
        __syncthreads();

        float acc[16];
        {
            float x0 = xs[R], x1 = xs[R + 8];
            const float* up = ub + g*256;
#pragma unroll
            for (int nb = 0; nb < 4; ++nb) {
                int c0 = gq*32 + nb*8 + t4*2;
                acc[nb*4+0] = fmaf(x0, up[c0],   up[128 + c0]);
                acc[nb*4+1] = fmaf(x0, up[c0+1], up[128 + c0 + 1]);
                acc[nb*4+2] = fmaf(x1, up[c0],   up[128 + c0]);
                acc[nb*4+3] = fmaf(x1, up[c0+1], up[128 + c0 + 1]);
            }
        }
        unsigned wb0 = wB + (unsigned)(g & 1)*65536u;
        unsigned wb1 = wb0 + 32768u;
#pragma unroll
        for (int kb = 0; kb < 8; ++kb) {
            unsigned ah[4], al[4], bh[8], bl[8];
            unsigned ao  = (unsigned)(rowA*256  + (((2*kb + jA) ^ (rowA  & 7)) << 4));
            unsigned bo0 = (unsigned)(rowB0*256 + (((2*kb + jB) ^ (rowB0 & 7)) << 4));
            unsigned bo1 = (unsigned)(rowB1*256 + (((2*kb + jB) ^ (rowB1 & 7)) << 4));
            LDX4(ah, aHiB + ao);
            LDX4(al, aLoB + ao);
            LDX4(bh + 0, wb0 + bo0); LDX4(bh + 4, wb0 + bo1);
            LDX4(bl + 0, wb1 + bo0); LDX4(bl + 4, wb1 + bo1);
            MMA(acc+0,  ah, bh[0], bh[1]); MMA(acc+0,  al, bh[0], bh[1]); MMA(acc+0,  ah, bl[0], bl[1]);
            MMA(acc+4,  ah, bh[2], bh[3]); MMA(acc+4,  al, bh[2], bh[3]); MMA(acc+4,  ah, bl[2], bl[3]);
            MMA(acc+8,  ah, bh[4], bh[5]); MMA(acc+8,  al, bh[4], bh[5]); MMA(acc+8,  ah, bl[4], bl[5]);
            MMA(acc+12, ah, bh[6], bh[7]); MMA(acc+12, al, bh[6], bh[7]); MMA(acc+12, ah, bl[6], bl[7]);
        }
        if (g == 0) {
#pragma unroll
            for (int e = 0; e < 16; ++e) h2[e] = tanhfast(acc[e]);
        } else if (g == 1) {
#pragma unroll
            for (int e = 0; e < 16; ++e) h2[e] *= sigf(acc[e]);
        } else if (g == 2) {
#pragma unroll
            for (int e = 0; e < 16; ++e) c[e] = fmaf(c[e], sigf(acc[e]), h2[e]);
        } else {
#pragma unroll
            for (int e = 0; e < 16; ++e) h2[e] = sigf(acc[e]) * tanhfast(c[e]);
        }
        __syncthreads();
    }
}

// ==== encoder ====
struct SEnc {
    __nv_bfloat16 W2[2][32768];
    __nv_bfloat16 Ahi[8192], Alo[8192];
    float ub[1024];
    float part[BC*5];
    float xs[BC], es[BC], den_s[BC];
};

__global__ void __launch_bounds__(NTHR, 1) enc_kernel(
    const float* __restrict__ x,
    const float* __restrict__ Uj, const float* __restrict__ Ui,
    const float* __restrict__ Uf, const float* __restrict__ Uo,
    const float* __restrict__ bj, const float* __restrict__ bi_,
    const float* __restrict__ bf, const float* __restrict__ bo,
    const float* __restrict__ Fa, const float* __restrict__ Fab,
    const float* __restrict__ Phi_w, const float* __restrict__ Phi_b,
    const float* __restrict__ Fbw, float* __restrict__ out)
{
    extern __shared__ char smraw[];
    SEnc* s = (SEnc*)smraw;
    const int tid = threadIdx.x;
    const int d = blockIdx.x >> 2;
    const int b0 = (blockIdx.x & 3)*BC;
    const int lane = tid & 31, w = tid >> 5;
    const int rg = w & 3, gq = w >> 2;
    const int t4 = lane & 3;
    const int R = rg*16 + (lane >> 2);
    const float fab = Fab[d];
    unsigned aHiB = sptr(s->Ahi), aLoB = sptr(s->Alo), wB = sptr(s->W2);

    if (tid < 4*NH) {
        int gate = tid >> 7, k = tid & 127;
        const float* Up = gate==0?Uj:gate==1?Ui:gate==2?Uf:Uo;
        const float* Bp = gate==0?bj:gate==1?bi_:gate==2?bf:bo;
        s->ub[gate*256 + k] = Up[d*NH + k];
        s->ub[gate*256 + 128 + k] = Bp[d*NH + k];
    }
    if (tid < BC) s->den_s[tid] = 0.f;
    for (int i = tid; i < 8192; i += NTHR) {
        s->Ahi[i] = __nv_bfloat16(0.f);
        s->Alo[i] = __nv_bfloat16(0.f);
    }
    float fa0[4], fa1[4];
#pragma unroll
    for (int nb = 0; nb < 4; ++nb) {
        int col = gq*32 + nb*8 + t4*2;
        fa0[nb] = Fa[(size_t)d*NH + col];
        fa1[nb] = Fa[(size_t)d*NH + col + 1];
    }
    float c[16], h2[16], num[16];
#pragma unroll
    for (int i = 0; i < 16; ++i) { c[i] = 0.f; num[i] = 0.f; }

    copyW2(wB, d, 0, tid);
    __syncthreads();

    for (int t = 0; t < NT; ++t) {
        if (tid < BC) s->xs[tid] = x[((size_t)(b0 + tid)*NT + t)*ND + d];

        cell_hmma(wB, aHiB, aLoB, s->ub, s->xs, d, tid, lane, w, c, h2, t == NT - 1);

        {
            size_t o0 = O_OFS + (((size_t)(b0 + R)*NT + t)*ND + d)*NH;
            size_t o1 = O_OFS + (((size_t)(b0 + R + 8)*NT + t)*ND + d)*NH;
            char* ahp = (char*)s->Ahi; char* alp = (char*)s->Alo;
            float p0 = 0.f, p1 = 0.f;
#pragma unroll
            for (int nb = 0; nb < 4; ++nb) {
                int col = gq*32 + nb*8 + t4*2;
                float h00 = h2[nb*4+0], h01 = h2[nb*4+1];
                float h10 = h2[nb*4+2], h11 = h2[nb*4+3];
                *(float2*)(out + o0 + col) = make_float2(h00, h01);
                *(float2*)(out + o1 + col) = make_float2(h10, h11);
                p0 = fmaf(h00, fa0[nb], fmaf(h01, fa1[nb], p0));
                p1 = fmaf(h10, fa0[nb], fmaf(h11, fa1[nb], p1));
                unsigned sw0 = (unsigned)(R*256 + (((col>>3) ^ (R & 7)) << 4) + t4*4);
                unsigned sw1 = (unsigned)((R+8)*256 + (((col>>3) ^ ((R+8) & 7)) << 4) + t4*4);
                unsigned hv, lv;
                splitbf(h00, h01, hv, lv);
                *(unsigned*)(ahp + sw0) = hv; *(unsigned*)(alp + sw0) = lv;
                splitbf(h10, h11, hv, lv);
                *(unsigned*)(ahp + sw1) = hv; *(unsigned*)(alp + sw1) = lv;
            }
            p0 += __shfl_xor_sync(0xffffffffu, p0, 1);
            p0 += __shfl_xor_sync(0xffffffffu, p0, 2);
            p1 += __shfl_xor_sync(0xffffffffu, p1, 1);
            p1 += __shfl_xor_sync(0xffffffffu, p1, 2);
            if (t4 == 0) { s->part[R*5 + gq] = p0; s->part[(R+8)*5 + gq] = p1; }
        }
        __syncthreads();
        if (tid < 256) {
            int r2 = tid >> 2, q = tid & 3;
            float v = s->part[r2*5 + q];
            v += __shfl_xor_sync(0xffffffffu, v, 1);
            v += __shfl_xor_sync(0xffffffffu, v, 2);
            if (q == 0) {
                float e = __expf(tanhfast(v + fab));
                s->es[r2] = e;
                s->den_s[r2] += e;
                out[A_OFS + ((size_t)(b0 + r2)*NT + t)*ND + d] = e;
            }
        }
        __syncthreads();
        {
            float e0 = s->es[R], e1 = s->es[R + 8];
#pragma unroll
            for (int nb = 0; nb < 4; ++nb) {
                num[nb*4+0] = fmaf(e0, h2[nb*4+0], num[nb*4+0]);
                num[nb*4+1] = fmaf(e0, h2[nb*4+1], num[nb*4+1]);
                num[nb*4+2] = fmaf(e1, h2[nb*4+2], num[nb*4+2]);
                num[nb*4+3] = fmaf(e1, h2[nb*4+3], num[nb*4+3]);
            }
        }
    }

    // ---- handoff ----
    float* gs = (float*)s->W2;
    {
        float inv0 = __fdividef(1.f, s->den_s[R]);
        float inv1 = __fdividef(1.f, s->den_s[R + 8]);
        size_t g0o = ((size_t)d*NB + b0 + R)*NH;
        size_t g1o = ((size_t)d*NB + b0 + R + 8)*NH;
#pragma unroll
        for (int nb = 0; nb < 4; ++nb) {
            int col = gq*32 + nb*8 + t4*2;
            *(float2*)(g_h + g0o + col) = make_float2(h2[nb*4+0], h2[nb*4+1]);
            *(float2*)(g_h + g1o + col) = make_float2(h2[nb*4+2], h2[nb*4+3]);
            *(float2*)(g_c + g0o + col) = make_float2(c[nb*4+0], c[nb*4+1]);
            *(float2*)(g_c + g1o + col) = make_float2(c[nb*4+2], c[nb*4+3]);
            gs[R*GST + col]         = num[nb*4+0]*inv0;
            gs[R*GST + col + 1]     = num[nb*4+1]*inv0;
            gs[(R+8)*GST + col]     = num[nb*4+2]*inv1;
            gs[(R+8)*GST + col + 1] = num[nb*4+3]*inv1;
        }
    }
    if (tid < BC) g_den[(size_t)(b0 + tid)*ND + d] = s->den_s[tid];
    __syncthreads();
    {   // mu_g
        int outc = tid & 31, bg = tid >> 5;
        float a4[4];
        float pb = Phi_b[outc];
#pragma unroll
        for (int r = 0; r < 4; ++r) a4[r] = pb;
#pragma unroll 2
        for (int k = 0; k < NH; ++k) {
            float pg = Phi_w[k*NOUT + outc];
#pragma unroll
            for (int r = 0; r < 4; ++r)
                a4[r] = fmaf(gs[(bg*4 + r)*GST + k], pg, a4[r]);
        }
#pragma unroll
        for (int r = 0; r < 4; ++r)
            g_mug[(((size_t)(b0 + bg*4 + r))*ND + d)*NOUT + outc] = a4[r];
    }
    {   // bt_g
        int b = tid >> 3, seg = tid & 7;
        float a = 0.f;
#pragma unroll
        for (int kk = 0; kk < 16; ++kk) {
            int k = seg*16 + kk;
            a = fmaf(gs[b*GST + k], Fbw[k], a);
        }
        a += __shfl_xor_sync(0xffffffffu, a, 1);
        a += __shfl_xor_sync(0xffffffffu, a, 2);
        a += __shfl_xor_sync(0xffffffffu, a, 4);
        if (seg == 0) g_btg[(size_t)(b0 + b)*ND + d] = a;
    }
}

// ==== alphas finalize ====
__global__ void alphas_fin_kernel(float* __restrict__ out) {
    int i = blockIdx.x*256 + threadIdx.x;
    if (i >= A_CNT) return;
    int b = i / (NT*ND), d = i & (ND-1);
    out[A_OFS + i] = __fdividef(out[A_OFS + i], g_den[(size_t)b*ND + d]);
}

// ==== persistent forecast with HMMA cell ====
struct SFc {
    __nv_bfloat16 W2[2][32768];
    __nv_bfloat16 Ahi[8192], Alo[8192];
    float ub[1024];
    float xs[BC];
    float hs[BC*GST];
    float phi_s[NH*NOUT];
    float fbw_s[NH];
};

__device__ __forceinline__ void grid_bar() {
    __syncthreads();
    if (threadIdx.x == 0) {
        __threadfence();
        unsigned gen = *(volatile unsigned*)&g_gen;
        if (atomicAdd(&g_cnt, 1u) == NCTA - 1u) {
            g_cnt = 0u; __threadfence(); atomicAdd(&g_gen, 1u);
        } else {
            while (*(volatile unsigned*)&g_gen == gen) __nanosleep(64);
        }
        __threadfence();
    }
    __syncthreads();
}

__global__ void __launch_bounds__(NTHR, 1) fc_kernel(
    const float* __restrict__ Uj, const float* __restrict__ Ui,
    const float* __restrict__ Uf, const float* __restrict__ Uo,
    const float* __restrict__ bj, const float* __restrict__ bi_,
    const float* __restrict__ bf, const float* __restrict__ bo,
    const float* __restrict__ Phi_w, const float* __restrict__ Fbw,
    const float* __restrict__ Fbb,
    const float* __restrict__ proj_w, const float* __restrict__ proj_b,
    float* __restrict__ out)
{
    extern __shared__ char smraw[];
    SFc* s = (SFc*)smraw;
    const int tid = threadIdx.x;
    const int d = blockIdx.x >> 2;
    const int b0 = (blockIdx.x & 3)*BC;
    const int lane = tid & 31, w = tid >> 5;
    const int rg = w & 3, gq = w >> 2;
    const int t4 = lane & 3;
    const int R = rg*16 + (lane >> 2);
    const int outc = tid & 31, bg = tid >> 5;
    const int bb_ = tid >> 3, seg = tid & 7;
    unsigned aHiB = sptr(s->Ahi), aLoB = sptr(s->Alo), wB = sptr(s->W2);

    copyW2(wB, d, 0, tid);

    if (tid < 4*NH) {
        int gate = tid >> 7, k = tid & 127;
        const float* Up = gate==0?Uj:gate==1?Ui:gate==2?Uf:Uo;
        const float* Bp = gate==0?bj:gate==1?bi_:gate==2?bf:bo;
        s->ub[gate*256 + k] = Up[d*NH + k];
        s->ub[gate*256 + 128 + k] = Bp[d*NH + k];
    }
    for (int i = tid; i < NH*NOUT; i += NTHR)
        s->phi_s[i] = Phi_w[(NH + (i >> 5))*NOUT + (i & 31)];
    if (tid < NH) s->fbw_s[tid] = Fbw[NH + tid];

    // load h into hs + A tiles
    for (int i = tid; i < BC*64; i += NTHR) {
        int b = i >> 6, kp = (i & 63)*2;
        size_t go = ((size_t)d*NB + b0 + b)*NH + kp;
        float h0v = g_h[go], h1v = g_h[go + 1];
        s->hs[b*GST + kp] = h0v;
        s->hs[b*GST + kp + 1] = h1v;
        unsigned hv, lv;
        splitbf(h0v, h1v, hv, lv);
        unsigned sw = (unsigned)(b*256 + (((kp>>3) ^ (b & 7)) << 4) + (kp & 7)*2);
        *(unsigned*)((char*)s->Ahi + sw) = hv;
        *(unsigned*)((char*)s->Alo + sw) = lv;
    }

    float c[16], h2[16];
    {
        size_t g0o = ((size_t)d*NB + b0 + R)*NH;
        size_t g1o = ((size_t)d*NB + b0 + R + 8)*NH;
#pragma unroll
        for (int nb = 0; nb < 4; ++nb) {
            int col = gq*32 + nb*8 + t4*2;
            float2 c0v = *(const float2*)(g_c + g0o + col);
            float2 c1v = *(const float2*)(g_c + g1o + col);
            c[nb*4+0] = c0v.x; c[nb*4+1] = c0v.y;
            c[nb*4+2] = c1v.x; c[nb*4+3] = c1v.y;
        }
    }
    float mug[4];
#pragma unroll
    for (int r = 0; r < 4; ++r)
        mug[r] = g_mug[(((size_t)(b0 + bg*4 + r))*ND + d)*NOUT + outc];
    const float btg = g_btg[(size_t)(b0 + bb_)*ND + d] + Fbb[0];
    __syncthreads();

    for (int f = 0; f < NF; ++f) {
        const int p = f & 1;
        {   // mu = mu_g + h . Phi_bot
            float a4[4];
#pragma unroll
            for (int r = 0; r < 4; ++r) a4[r] = mug[r];
#pragma unroll 2
            for (int k = 0; k < NH; ++k) {
                float phv = s->phi_s[k*NOUT + outc];
#pragma unroll
                for (int r = 0; r < 4; ++r)
                    a4[r] = fmaf(s->hs[(bg*4 + r)*GST + k], phv, a4[r]);
            }
#pragma unroll
            for (int r = 0; r < 4; ++r)
                g_mu2[p][(((size_t)(b0 + bg*4 + r))*ND + d)*NOUT + outc] = a4[r];
        }
        {   // bt
            float a = 0.f;
#pragma unroll
            for (int kk = 0; kk < 16; ++kk) {
                int k = seg*16 + kk;
                a = fmaf(s->hs[bb_*GST + k], s->fbw_s[k], a);
            }
            a += __shfl_xor_sync(0xffffffffu, a, 1);
            a += __shfl_xor_sync(0xffffffffu, a, 2);
            a += __shfl_xor_sync(0xffffffffu, a, 4);
            if (seg == 0)
                g_bt2[p][(size_t)(b0 + bb_)*ND + d] = __expf(tanhfast(a + btg));
        }
        __threadfence();
        grid_bar();

        // reduce over D: betas, y, prev -> xs
#pragma unroll
        for (int rr = 0; rr < 4; ++rr) {
            int b = w*4 + rr;
            float bt = g_bt2[p][(size_t)(b0 + b)*ND + lane];
            float ssum = bt;
#pragma unroll
            for (int o = 16; o > 0; o >>= 1)
                ssum += __shfl_xor_sync(0xffffffffu, ssum, o);
            float beta = __fdividef(bt, ssum);
            if (d == 0)
                out[B_OFS + ((size_t)(b0 + b)*NF + f)*ND + lane] = beta;
            float y = 0.f;
            const float* mup = g_mu2[p] + ((size_t)(b0 + b)*ND)*NOUT + lane;
#pragma unroll
            for (int d2 = 0; d2 < ND; ++d2)
                y = fmaf(__shfl_sync(0xffffffffu, beta, d2), mup[d2*NOUT], y);
            if (d == 0)
                out[((size_t)(b0 + b)*NF + f)*NOUT + lane] = y;
            float pr = y * proj_w[lane*ND + d];
#pragma unroll
            for (int o = 16; o > 0; o >>= 1)
                pr += __shfl_xor_sync(0xffffffffu, pr, o);
            if (lane == 0) s->xs[b] = pr + proj_b[d];
        }
        if (f == NF - 1) break;

        cell_hmma(wB, aHiB, aLoB, s->ub, s->xs, d, tid, lane, w, c, h2, f == NF - 2);

        {   // write new h -> hs + A tiles
            char* ahp = (char*)s->Ahi; char* alp = (char*)s->Alo;
#pragma unroll
            for (int nb = 0; nb < 4; ++nb) {
                int col = gq*32 + nb*8 + t4*2;
                float h00 = h2[nb*4+0], h01 = h2[nb*4+1];
                float h10 = h2[nb*4+2], h11 = h2[nb*4+3];
                s->hs[R*GST + col] = h00; s->hs[R*GST + col + 1] = h01;
                s->hs[(R+8)*GST + col] = h10; s->hs[(R+8)*GST + col + 1] = h11;
                unsigned sw0 = (unsigned)(R*256 + (((col>>3) ^ (R & 7)) << 4) + t4*4);
                unsigned sw1 = (unsigned)((R+8)*256 + (((col>>3) ^ ((R+8) & 7)) << 4) + t4*4);
                unsigned hv, lv;
                splitbf(h00, h01, hv, lv);
                *(unsigned*)(ahp + sw0) = hv; *(unsigned*)(alp + sw0) = lv;
                splitbf(h10, h11, hv, lv);
                *(unsigned*)(ahp + sw1) = hv; *(unsigned*)(alp + sw1) = lv;
            }
        }
        __syncthreads();
    }
}

// ==== launch ====
extern "C" void kernel_launch(void* const* d_in, const int* in_sizes, int n_in,
                              void* d_out, int out_size) {
    const float* x   = (const float*)d_in[0];
    const float* Uj  = (const float*)d_in[1];
    const float* Ui  = (const float*)d_in[2];
    const float* Uf  = (const float*)d_in[3];
    const float* Uo  = (const float*)d_in[4];
    const float* Wj  = (const float*)d_in[5];
    const float* Wi  = (const float*)d_in[6];
    const float* Wf  = (const float*)d_in[7];
    const float* Wo  = (const float*)d_in[8];
    const float* bj  = (const float*)d_in[9];
    const float* bi  = (const float*)d_in[10];
    const float* bf  = (const float*)d_in[11];
    const float* bo  = (const float*)d_in[12];
    const float* Fa  = (const float*)d_in[13];
    const float* Fab = (const float*)d_in[14];
    const float* Fbw = (const float*)d_in[15];
    const float* Fbb = (const float*)d_in[16];
    const float* Phw = (const float*)d_in[17];
    const float* Phb = (const float*)d_in[18];
    const float* prw = (const float*)d_in[19];
    const float* prb = (const float*)d_in[20];
    float* out = (float*)d_out;

    int smE = (int)sizeof(SEnc);
    int smF = (int)sizeof(SFc);
    cudaFuncSetAttribute(enc_kernel, cudaFuncAttributeMaxDynamicSharedMemorySize, smE);
    cudaFuncSetAttribute(fc_kernel,  cudaFuncAttributeMaxDynamicSharedMemorySize, smF);

    prep_kernel<<<4096, 256>>>(Wj, Wi, Wf, Wo);
    enc_kernel<<<NCTA, NTHR, smE>>>(x, Uj,Ui,Uf,Uo, bj,bi,bf,bo,
                                    Fa, Fab, Phw, Phb, Fbw, out);
    alphas_fin_kernel<<<(A_CNT + 255)/256, 256>>>(out);
    fc_kernel<<<NCTA, NTHR, smF>>>(Uj,Ui,Uf,Uo, bj,bi,bf,bo,
                                   Phw, Fbw, Fbb, prw, prb, out);
}

// round 15
// speedup vs baseline: 1.1485x; 1.1485x over previous
#include <cuda_runtime.h>
#include <cuda_bf16.h>

#define NB 256
#define NT 96
#define ND 32
#define NOUT 32
#define NH 128
#define NF 24
#define BC 64
#define NCTA 128
#define NTHR 512
#define HS2 129
#define GST 130

#define F_CNT (NB*NF*NOUT)
#define A_OFS F_CNT
#define A_CNT (NB*NT*ND)
#define B_OFS (A_OFS + A_CNT)
#define O_OFS (B_OFS + NB*NF*ND)

typedef unsigned long long ull;

__device__ float g_h[ND*NB*NH];
__device__ float g_c[ND*NB*NH];
__device__ float g_den[NB*ND];
__device__ float g_mug[NB*ND*NOUT];
__device__ float g_btg[NB*ND];
__device__ float g_mu2[2][NB*ND*NOUT];
__device__ float g_bt2[2][NB*ND];
__device__ unsigned g_cnt;
__device__ unsigned g_gen;
__device__ __nv_bfloat16 g_Wimg[4*32*32768];  // [gate][d][hi 32KB | lo 32KB], swizzled

// ---- helpers ----
__device__ __forceinline__ ull pack2(float lo, float hi) {
    ull r; asm("mov.b64 %0, {%1, %2};" : "=l"(r)
        : "r"(__float_as_uint(lo)), "r"(__float_as_uint(hi)));
    return r;
}
__device__ __forceinline__ ull dup2(float v) {
    ull r; unsigned u = __float_as_uint(v);
    asm("mov.b64 %0, {%1, %1};" : "=l"(r) : "r"(u));
    return r;
}
__device__ __forceinline__ void unpack2(ull p, float &lo, float &hi) {
    unsigned a, b;
    asm("mov.b64 {%0, %1}, %2;" : "=r"(a), "=r"(b) : "l"(p));
    lo = __uint_as_float(a); hi = __uint_as_float(b);
}
__device__ __forceinline__ void fma2(ull &acc, ull a, ull b) {
    asm("fma.rn.f32x2 %0, %1, %2, %0;" : "+l"(acc) : "l"(a), "l"(b));
}
__device__ __forceinline__ float sigf(float x) { return __fdividef(1.f, 1.f + __expf(-x)); }
__device__ __forceinline__ float tanhfast(float x) {
    float e = __expf(-2.f * x);
    return __fdividef(1.f - e, 1.f + e);
}
__device__ __forceinline__ void cp16(unsigned dst, const void* src) {
    asm volatile("cp.async.cg.shared.global [%0], [%1], 16;" :: "r"(dst), "l"(src));
}
__device__ __forceinline__ void cp_commit() { asm volatile("cp.async.commit_group;"); }
template<int N> __device__ __forceinline__ void cp_wait() {
    asm volatile("cp.async.wait_group %0;" :: "n"(N));
}
__device__ __forceinline__ unsigned sptr(const void* p) {
    return (unsigned)__cvta_generic_to_shared(p);
}
#define LDX4(r, a) asm volatile("ldmatrix.sync.aligned.m8n8.x4.shared.b16 {%0,%1,%2,%3},[%4];" \
    : "=r"((r)[0]),"=r"((r)[1]),"=r"((r)[2]),"=r"((r)[3]) : "r"(a))
#define MMAI(dd, a, b0v, b1v) asm volatile( \
    "mma.sync.aligned.m16n8k16.row.col.f32.bf16.bf16.f32 {%0,%1,%2,%3},{%4,%5,%6,%7},{%8,%9},{%0,%1,%2,%3};" \
    : "+f"((dd)[0]),"+f"((dd)[1]),"+f"((dd)[2]),"+f"((dd)[3]) \
    : "r"((a)[0]),"r"((a)[1]),"r"((a)[2]),"r"((a)[3]),"r"(b0v),"r"(b1v))

__device__ __forceinline__ void splitbf(float a, float b, unsigned &hi, unsigned &lo) {
    __nv_bfloat16 ah = __float2bfloat16(a), bh = __float2bfloat16(b);
    __nv_bfloat16 al2 = __float2bfloat16(a - __bfloat162float(ah));
    __nv_bfloat16 bl2 = __float2bfloat16(b - __bfloat162float(bh));
    hi = (unsigned)*(unsigned short*)&ah | ((unsigned)*(unsigned short*)&bh << 16);
    lo = (unsigned)*(unsigned short*)&al2 | ((unsigned)*(unsigned short*)&bl2 << 16);
}

// ==== prep: W^T bf16 hi/lo swizzled images ====
__global__ void prep_kernel(const float* __restrict__ Wj, const float* __restrict__ Wi,
                            const float* __restrict__ Wf, const float* __restrict__ Wo) {
    int idx = blockIdx.x*256 + threadIdx.x;
    if (idx >= 4*32*128*64) return;
    int i2 = idx & 63, n = (idx>>6)&127, dd = (idx>>13)&31, g = idx>>18;
    const float* W = (g==0?Wj:g==1?Wi:g==2?Wf:Wo) + (size_t)dd*NH*NH;
    int k = 2*i2;
    float w0 = W[k*NH + n], w1 = W[(k+1)*NH + n];
    unsigned hv, lv;
    splitbf(w0, w1, hv, lv);
    unsigned off = (unsigned)(n*128 + (((k>>3) ^ (n&7))<<3) + (k&7));
    __nv_bfloat16* base = g_Wimg + ((size_t)g*32 + dd)*32768;
    *(unsigned*)((char*)base + off*2)         = hv;
    *(unsigned*)((char*)base + 32768 + off*2) = lv;
}

// ==== encoder: W_hi resident, W_lo streamed ====
struct SEnc {
    __nv_bfloat16 Whi[4*16384];   // 128KB resident (reused as float gs staging at end)
    __nv_bfloat16 Wlo[16384];     // 32KB streamed buffer
    __nv_bfloat16 Ahi[8192], Alo[8192];  // 2 x 16KB
    float ub[1024];
    float part[BC*5];
    float xs[BC], es[BC], den_s[BC];
};

// copy one gate's 32KB lo image (4 x 16B per thread)
__device__ __forceinline__ void copyLo(unsigned wloB, int d, int gi, int tid) {
    const char* src = (const char*)(g_Wimg + ((size_t)gi*32 + d)*32768) + 32768 + tid*16;
    unsigned dst = wloB + (unsigned)tid*16u;
#pragma unroll
    for (int j = 0; j < 4; ++j) cp16(dst + j*8192u, src + j*8192);
    cp_commit();
}

__global__ void __launch_bounds__(NTHR, 1) enc_kernel(
    const float* __restrict__ x,
    const float* __restrict__ Uj, const float* __restrict__ Ui,
    const float* __restrict__ Uf, const float* __restrict__ Uo,
    const float* __restrict__ bj, const float* __restrict__ bi_,
    const float* __restrict__ bf, const float* __restrict__ bo,
    const float* __restrict__ Fa, const float* __restrict__ Fab,
    const float* __restrict__ Phi_w, const float* __restrict__ Phi_b,
    const float* __restrict__ Fbw, float* __restrict__ out)
{
    extern __shared__ char smraw[];
    SEnc* s = (SEnc*)smraw;
    const int tid = threadIdx.x;
    const int d = blockIdx.x >> 2;
    const int b0 = (blockIdx.x & 3)*BC;
    const int lane = tid & 31, w = tid >> 5;
    const int rg = w & 3, gq = w >> 2;
    const int t4 = lane & 3;
    const int R = rg*16 + (lane >> 2);
    const int l8 = lane & 7, m = lane >> 3;
    const int rowA = rg*16 + ((m & 1) << 3) + l8; const int jA = (m >> 1) & 1;
    const int rowB0 = gq*32 + ((m >> 1) << 3) + l8; const int jB = m & 1;
    const int rowB1 = rowB0 + 16;
    const float fab = Fab[d];
    unsigned aHiB = sptr(s->Ahi), aLoB = sptr(s->Alo);
    unsigned whiB = sptr(s->Whi), wloB = sptr(s->Wlo);

    // init: resident hi images (4 x 32KB) + lo[0]
    {
        unsigned dstb = whiB + (unsigned)tid*16u;
#pragma unroll
        for (int gi = 0; gi < 4; ++gi) {
            const char* src = (const char*)(g_Wimg + ((size_t)gi*32 + d)*32768) + tid*16;
#pragma unroll
            for (int j = 0; j < 4; ++j)
                cp16(dstb + (unsigned)gi*32768u + j*8192u, src + j*8192);
        }
        cp_commit();
    }
    copyLo(wloB, d, 0, tid);

    if (tid < 4*NH) {
        int gate = tid >> 7, k = tid & 127;
        const float* Up = gate==0?Uj:gate==1?Ui:gate==2?Uf:Uo;
        const float* Bp = gate==0?bj:gate==1?bi_:gate==2?bf:bo;
        s->ub[gate*256 + k] = Up[d*NH + k];
        s->ub[gate*256 + 128 + k] = Bp[d*NH + k];
    }
    if (tid < BC) s->den_s[tid] = 0.f;
    for (int i = tid; i < 8192; i += NTHR) {
        s->Ahi[i] = __nv_bfloat16(0.f);
        s->Alo[i] = __nv_bfloat16(0.f);
    }
    float fa0[4], fa1[4];
#pragma unroll
    for (int nb = 0; nb < 4; ++nb) {
        int col = gq*32 + nb*8 + t4*2;
        fa0[nb] = Fa[(size_t)d*NH + col];
        fa1[nb] = Fa[(size_t)d*NH + col + 1];
    }
    float c[16], h2[16], num[16];
#pragma unroll
    for (int i = 0; i < 16; ++i) { c[i] = 0.f; num[i] = 0.f; }
    __syncthreads();

    for (int t = 0; t < NT; ++t) {
        if (tid < BC) s->xs[tid] = x[((size_t)(b0 + tid)*NT + t)*ND + d];
        __syncthreads();

#pragma unroll
        for (int g = 0; g < 4; ++g) {
            float acc[16];
            {
                float x0 = s->xs[R], x1 = s->xs[R + 8];
                const float* up = s->ub + g*256;
#pragma unroll
                for (int nb = 0; nb < 4; ++nb) {
                    int c0 = gq*32 + nb*8 + t4*2;
                    acc[nb*4+0] = fmaf(x0, up[c0],   up[128 + c0]);
                    acc[nb*4+1] = fmaf(x0, up[c0+1], up[128 + c0 + 1]);
                    acc[nb*4+2] = fmaf(x1, up[c0],   up[128 + c0]);
                    acc[nb*4+3] = fmaf(x1, up[c0+1], up[128 + c0 + 1]);
                }
            }
            // pass 1: resident hi W (AhiBhi + AloBhi)
            unsigned whg = whiB + (unsigned)g*32768u;
#pragma unroll
            for (int kb = 0; kb < 8; ++kb) {
                unsigned ah[4], al[4], bh[8];
                unsigned ao  = (unsigned)(rowA*256  + (((2*kb + jA) ^ (rowA  & 7)) << 4));
                unsigned bo0 = (unsigned)(rowB0*256 + (((2*kb + jB) ^ (rowB0 & 7)) << 4));
                unsigned bo1 = (unsigned)(rowB1*256 + (((2*kb + jB) ^ (rowB1 & 7)) << 4));
                LDX4(ah, aHiB + ao);
                LDX4(al, aLoB + ao);
                LDX4(bh + 0, whg + bo0); LDX4(bh + 4, whg + bo1);
                MMAI(acc+0,  ah, bh[0], bh[1]); MMAI(acc+0,  al, bh[0], bh[1]);
                MMAI(acc+4,  ah, bh[2], bh[3]); MMAI(acc+4,  al, bh[2], bh[3]);
                MMAI(acc+8,  ah, bh[4], bh[5]); MMAI(acc+8,  al, bh[4], bh[5]);
                MMAI(acc+12, ah, bh[6], bh[7]); MMAI(acc+12, al, bh[6], bh[7]);
            }
            cp_wait<0>();
            __syncthreads();          // lo[g] ready for everyone
            // pass 2: streamed lo W (AhiBlo)
#pragma unroll
            for (int kb = 0; kb < 8; ++kb) {
                unsigned ah[4], bl[8];
                unsigned ao  = (unsigned)(rowA*256  + (((2*kb + jA) ^ (rowA  & 7)) << 4));
                unsigned bo0 = (unsigned)(rowB0*256 + (((2*kb + jB) ^ (rowB0 & 7)) << 4));
                unsigned bo1 = (unsigned)(rowB1*256 + (((2*kb + jB) ^ (rowB1 & 7)) << 4));
                LDX4(ah, aHiB + ao);
                LDX4(bl + 0, wloB + bo0); LDX4(bl + 4, wloB + bo1);
                MMAI(acc+0,  ah, bl[0], bl[1]);
                MMAI(acc+4,  ah, bl[2], bl[3]);
                MMAI(acc+8,  ah, bl[4], bl[5]);
                MMAI(acc+12, ah, bl[6], bl[7]);
            }
            if (g == 0) {
#pragma unroll
                for (int e = 0; e < 16; ++e) h2[e] = tanhfast(acc[e]);
            } else if (g == 1) {
#pragma unroll
                for (int e = 0; e < 16; ++e) h2[e] *= sigf(acc[e]);
            } else if (g == 2) {
#pragma unroll
                for (int e = 0; e < 16; ++e) c[e] = fmaf(c[e], sigf(acc[e]), h2[e]);
            } else {
#pragma unroll
                for (int e = 0; e < 16; ++e) h2[e] = sigf(acc[e]) * tanhfast(c[e]);
            }
            __syncthreads();          // all warps done with lo buffer
            if (!(g == 3 && t == NT - 1))
                copyLo(wloB, d, (g + 1) & 3, tid);
        }

        // ---- epilogue (champion R13 code) ----
        {
            size_t o0 = O_OFS + (((size_t)(b0 + R)*NT + t)*ND + d)*NH;
            size_t o1 = O_OFS + (((size_t)(b0 + R + 8)*NT + t)*ND + d)*NH;
            char* ahp = (char*)s->Ahi; char* alp = (char*)s->Alo;
            float p0 = 0.f, p1 = 0.f;
#pragma unroll
            for (int nb = 0; nb < 4; ++nb) {
                int col = gq*32 + nb*8 + t4*2;
                float h00 = h2[nb*4+0], h01 = h2[nb*4+1];
                float h10 = h2[nb*4+2], h11 = h2[nb*4+3];
                *(float2*)(out + o0 + col) = make_float2(h00, h01);
                *(float2*)(out + o1 + col) = make_float2(h10, h11);
                p0 = fmaf(h00, fa0[nb], fmaf(h01, fa1[nb], p0));
                p1 = fmaf(h10, fa0[nb], fmaf(h11, fa1[nb], p1));
                unsigned sw0 = (unsigned)(R*256 + (((col>>3) ^ (R & 7)) << 4) + t4*4);
                unsigned sw1 = (unsigned)((R+8)*256 + (((col>>3) ^ ((R+8) & 7)) << 4) + t4*4);
                unsigned hv, lv;
                splitbf(h00, h01, hv, lv);
                *(unsigned*)(ahp + sw0) = hv; *(unsigned*)(alp + sw0) = lv;
                splitbf(h10, h11, hv, lv);
                *(unsigned*)(ahp + sw1) = hv; *(unsigned*)(alp + sw1) = lv;
            }
            p0 += __shfl_xor_sync(0xffffffffu, p0, 1);
            p0 += __shfl_xor_sync(0xffffffffu, p0, 2);
            p1 += __shfl_xor_sync(0xffffffffu, p1, 1);
            p1 += __shfl_xor_sync(0xffffffffu, p1, 2);
            if (t4 == 0) { s->part[R*5 + gq] = p0; s->part[(R+8)*5 + gq] = p1; }
        }
        __syncthreads();
        if (tid < 256) {
            int r2 = tid >> 2, q = tid & 3;
            float v = s->part[r2*5 + q];
            v += __shfl_xor_sync(0xffffffffu, v, 1);
            v += __shfl_xor_sync(0xffffffffu, v, 2);
            if (q == 0) {
                float e = __expf(tanhfast(v + fab));
                s->es[r2] = e;
                s->den_s[r2] += e;
                out[A_OFS + ((size_t)(b0 + r2)*NT + t)*ND + d] = e;
            }
        }
        __syncthreads();
        {
            float e0 = s->es[R], e1 = s->es[R + 8];
#pragma unroll
            for (int nb = 0; nb < 4; ++nb) {
                num[nb*4+0] = fmaf(e0, h2[nb*4+0], num[nb*4+0]);
                num[nb*4+1] = fmaf(e0, h2[nb*4+1], num[nb*4+1]);
                num[nb*4+2] = fmaf(e1, h2[nb*4+2], num[nb*4+2]);
                num[nb*4+3] = fmaf(e1, h2[nb*4+3], num[nb*4+3]);
            }
        }
    }

    // ---- handoff (champion R13 code; gs staged in Whi region) ----
    float* gs = (float*)s->Whi;
    {
        float inv0 = __fdividef(1.f, s->den_s[R]);
        float inv1 = __fdividef(1.f, s->den_s[R + 8]);
        size_t g0o = ((size_t)d*NB + b0 + R)*NH;
        size_t g1o = ((size_t)d*NB + b0 + R + 8)*NH;
#pragma unroll
        for (int nb = 0; nb < 4; ++nb) {
            int col = gq*32 + nb*8 + t4*2;
            *(float2*)(g_h + g0o + col) = make_float2(h2[nb*4+0], h2[nb*4+1]);
            *(float2*)(g_h + g1o + col) = make_float2(h2[nb*4+2], h2[nb*4+3]);
            *(float2*)(g_c + g0o + col) = make_float2(c[nb*4+0], c[nb*4+1]);
            *(float2*)(g_c + g1o + col) = make_float2(c[nb*4+2], c[nb*4+3]);
            gs[R*GST + col]         = num[nb*4+0]*inv0;
            gs[R*GST + col + 1]     = num[nb*4+1]*inv0;
            gs[(R+8)*GST + col]     = num[nb*4+2]*inv1;
            gs[(R+8)*GST + col + 1] = num[nb*4+3]*inv1;
        }
    }
    if (tid < BC) g_den[(size_t)(b0 + tid)*ND + d] = s->den_s[tid];
    __syncthreads();
    {   // mu_g
        int outc = tid & 31, bg = tid >> 5;
        float a4[4];
        float pb = Phi_b[outc];
#pragma unroll
        for (int r = 0; r < 4; ++r) a4[r] = pb;
#pragma unroll 2
        for (int k = 0; k < NH; ++k) {
            float pg = Phi_w[k*NOUT + outc];
#pragma unroll
            for (int r = 0; r < 4; ++r)
                a4[r] = fmaf(gs[(bg*4 + r)*GST + k], pg, a4[r]);
        }
#pragma unroll
        for (int r = 0; r < 4; ++r)
            g_mug[(((size_t)(b0 + bg*4 + r))*ND + d)*NOUT + outc] = a4[r];
    }
    {   // bt_g
        int b = tid >> 3, seg = tid & 7;
        float a = 0.f;
#pragma unroll
        for (int kk = 0; kk < 16; ++kk) {
            int k = seg*16 + kk;
            a = fmaf(gs[b*GST + k], Fbw[k], a);
        }
        a += __shfl_xor_sync(0xffffffffu, a, 1);
        a += __shfl_xor_sync(0xffffffffu, a, 2);
        a += __shfl_xor_sync(0xffffffffu, a, 4);
        if (seg == 0) g_btg[(size_t)(b0 + b)*ND + d] = a;
    }
}

// ==== alphas finalize ====
__global__ void alphas_fin_kernel(float* __restrict__ out) {
    int i = blockIdx.x*256 + threadIdx.x;
    if (i >= A_CNT) return;
    int b = i / (NT*ND), d = i & (ND-1);
    out[A_OFS + i] = __fdividef(out[A_OFS + i], g_den[(size_t)b*ND + d]);
}

// ==== fc (R13 scalar champion, verbatim) ====
struct SF {
    float Wt[2][4*32*128];
    ull   hdup[BC*HS2];
    float phi_s[NH*NOUT];
    float fbw_s[NH];
    float ub[4*2*NH];
    float xs[BC];
};

__device__ __forceinline__ void issue_tile(unsigned wtb, const float* __restrict__ gw,
                                           int tile, int q, int g) {
    unsigned dst = wtb + (unsigned)(g*4096 + q*4)*4u;
    const float4* src = (const float4*)(gw + tile*4096) + q;
#pragma unroll
    for (int j = 0; j < 8; ++j) cp16(dst + j*2048u, src + j*128);
    cp_commit();
}
__device__ __forceinline__ void compute_tile(const float* __restrict__ wt,
                                             const ull* __restrict__ h0p,
                                             const ull* __restrict__ h1p,
                                             int c0, ull* acc) {
    const float* base = wt + c0;
    ulonglong2 wa = *(const ulonglong2*)(base);
    ulonglong2 wb = *(const ulonglong2*)(base + 4);
    ull h0 = h0p[0], h1 = h1p[0];
#pragma unroll 4
    for (int kk = 0; kk < 32; ++kk) {
        ull h0n = h0p[kk+1], h1n = h1p[kk+1];
#pragma unroll
        for (int g = 0; g < 4; ++g) {
            const float* nb = base + (g == 3 ? (kk+1)*128 : (g+1)*4096 + kk*128);
            ulonglong2 wan = *(const ulonglong2*)(nb);
            ulonglong2 wbn = *(const ulonglong2*)(nb + 4);
            fma2(acc[g*8+0], h0, wa.x); fma2(acc[g*8+1], h0, wa.y);
            fma2(acc[g*8+2], h0, wb.x); fma2(acc[g*8+3], h0, wb.y);
            fma2(acc[g*8+4], h1, wa.x); fma2(acc[g*8+5], h1, wa.y);
            fma2(acc[g*8+6], h1, wb.x); fma2(acc[g*8+7], h1, wb.y);
            wa = wan; wb = wbn;
        }
        h0 = h0n; h1 = h1n;
    }
}
#define INITG(gg) { \
    const float* up = s->ub + (gg)*256 + c0; \
    float4 u0 = *(const float4*)(up);       float4 u1 = *(const float4*)(up + 4); \
    float4 v0 = *(const float4*)(up + 128); float4 v1 = *(const float4*)(up + 132); \
    acc[(gg)*8+0] = pack2(fmaf(xv0,u0.x,v0.x), fmaf(xv0,u0.y,v0.y)); \
    acc[(gg)*8+1] = pack2(fmaf(xv0,u0.z,v0.z), fmaf(xv0,u0.w,v0.w)); \
    acc[(gg)*8+2] = pack2(fmaf(xv0,u1.x,v1.x), fmaf(xv0,u1.y,v1.y)); \
    acc[(gg)*8+3] = pack2(fmaf(xv0,u1.z,v1.z), fmaf(xv0,u1.w,v1.w)); \
    acc[(gg)*8+4] = pack2(fmaf(xv1,u0.x,v0.x), fmaf(xv1,u0.y,v0.y)); \
    acc[(gg)*8+5] = pack2(fmaf(xv1,u0.z,v0.z), fmaf(xv1,u0.w,v0.w)); \
    acc[(gg)*8+6] = pack2(fmaf(xv1,u1.x,v1.x), fmaf(xv1,u1.y,v1.y)); \
    acc[(gg)*8+7] = pack2(fmaf(xv1,u1.z,v1.z), fmaf(xv1,u1.w,v1.w)); }

__device__ __forceinline__ void cell_pipe(
    SF* s, unsigned wt0, unsigned wt1,
    const float* __restrict__ gw, int q, int g,
    int lane, int c0, float* c, float* h2, bool pf)
{
    ull acc[32];
    __syncthreads();
    {
        float xv0 = s->xs[lane], xv1 = s->xs[lane + 32];
        INITG(0); INITG(1); INITG(2); INITG(3);
    }
    const ull* h0b = s->hdup + (size_t)lane*HS2;
    const ull* h1b = s->hdup + (size_t)(lane + 32)*HS2;
#pragma unroll 1
    for (int t = 0; t < 4; ++t) {
        if (t < 3 || pf) cp_wait<1>(); else cp_wait<0>();
        __syncthreads();
        const float* wt = (t & 1) ? (const float*)(s->Wt[1]) : (const float*)(s->Wt[0]);
        compute_tile(wt, h0b + t*32, h1b + t*32, c0, acc);
        __syncthreads();
        if (t < 2 || pf) issue_tile((t & 1) ? wt1 : wt0, gw, (t + 2) & 3, q, g);
    }
#pragma unroll
    for (int e = 0; e < 8; ++e) {
        int ii = (e >> 2)*8 + (e & 3)*2;
        float jl, jh, il, ih, fl, fh, ol, oh;
        unpack2(acc[e], jl, jh);
        unpack2(acc[8+e], il, ih);
        unpack2(acc[16+e], fl, fh);
        unpack2(acc[24+e], ol, oh);
        float cl = fmaf(c[ii],   sigf(fl), sigf(il)*tanhfast(jl));
        float ch = fmaf(c[ii+1], sigf(fh), sigf(ih)*tanhfast(jh));
        c[ii] = cl; c[ii+1] = ch;
        h2[ii]   = sigf(ol)*tanhfast(cl);
        h2[ii+1] = sigf(oh)*tanhfast(ch);
    }
}
__device__ __forceinline__ void grid_bar() {
    __syncthreads();
    if (threadIdx.x == 0) {
        __threadfence();
        unsigned gen = *(volatile unsigned*)&g_gen;
        if (atomicAdd(&g_cnt, 1u) == NCTA - 1u) {
            g_cnt = 0u; __threadfence(); atomicAdd(&g_gen, 1u);
        } else {
            while (*(volatile unsigned*)&g_gen == gen) __nanosleep(64);
        }
        __threadfence();
    }
    __syncthreads();
}

__global__ void __launch_bounds__(NTHR, 1) fc_kernel(
    const float* __restrict__ Uj, const float* __restrict__ Ui,
    const float* __restrict__ Uf, const float* __restrict__ Uo,
    const float* __restrict__ Wj, const float* __restrict__ Wi,
    const float* __restrict__ Wf, const float* __restrict__ Wo,
    const float* __restrict__ bj, const float* __restrict__ bi_,
    const float* __restrict__ bf, const float* __restrict__ bo,
    const float* __restrict__ Phi_w, const float* __restrict__ Fbw,
    const float* __restrict__ Fbb,
    const float* __restrict__ proj_w, const float* __restrict__ proj_b,
    float* __restrict__ out)
{
    extern __shared__ char smem_raw[];
    SF* s = (SF*)smem_raw;
    const int tid = threadIdx.x;
    const int d = blockIdx.x >> 2;
    const int b0 = (blockIdx.x & 3)*BC;
    const int lane = tid & 31, w = tid >> 5;
    const int c0 = w*8, q = tid & 127, g = tid >> 7;
    const int outc = tid & 31, bg = tid >> 5;
    const int bb_ = tid >> 3, seg = tid & 7;

    const size_t dHH = (size_t)d*NH*NH;
    const float* gw = (g==0?Wj:g==1?Wi:g==2?Wf:Wo) + dHH;
    unsigned wt0 = sptr(s->Wt[0]), wt1 = sptr(s->Wt[1]);

    issue_tile(wt0, gw, 0, q, g);
    issue_tile(wt1, gw, 1, q, g);

    for (int i = tid; i < BC*NH; i += NTHR) {
        int b = i >> 7, k = i & 127;
        s->hdup[b*HS2 + k] = dup2(g_h[((size_t)d*NB + b0 + b)*NH + k]);
    }
    for (int i = tid; i < NH*NOUT; i += NTHR)
        s->phi_s[i] = Phi_w[(NH + (i >> 5))*NOUT + (i & 31)];
    if (tid < NH) s->fbw_s[tid] = Fbw[NH + tid];
    if (tid < 4*NH) {
        int gate = tid >> 7, k = tid & 127;
        const float* Up = gate==0?Uj:gate==1?Ui:gate==2?Uf:Uo;
        const float* Bp = gate==0?bj:gate==1?bi_:gate==2?bf:bo;
        s->ub[gate*256 + k] = Up[d*NH + k];
        s->ub[gate*256 + 128 + k] = Bp[d*NH + k];
    }

    float c[16], h2[16];
    {
        size_t g0 = ((size_t)d*NB + b0 + lane)*NH + c0;
        size_t g1 = ((size_t)d*NB + b0 + lane + 32)*NH + c0;
        float4 a0 = *(const float4*)(g_c + g0);
        float4 a1 = *(const float4*)(g_c + g0 + 4);
        float4 a2 = *(const float4*)(g_c + g1);
        float4 a3 = *(const float4*)(g_c + g1 + 4);
        c[0]=a0.x;c[1]=a0.y;c[2]=a0.z;c[3]=a0.w;
        c[4]=a1.x;c[5]=a1.y;c[6]=a1.z;c[7]=a1.w;
        c[8]=a2.x;c[9]=a2.y;c[10]=a2.z;c[11]=a2.w;
        c[12]=a3.x;c[13]=a3.y;c[14]=a3.z;c[15]=a3.w;
    }
    float mug[4];
#pragma unroll
    for (int r = 0; r < 4; ++r)
        mug[r] = g_mug[(((size_t)(b0 + bg*4 + r))*ND + d)*NOUT + outc];
    const float btg = g_btg[(size_t)(b0 + bb_)*ND + d] + Fbb[0];
    __syncthreads();

    for (int f = 0; f < NF; ++f) {
        const int p = f & 1;
        {
            float a4[4];
#pragma unroll
            for (int r = 0; r < 4; ++r) a4[r] = mug[r];
#pragma unroll 2
            for (int k = 0; k < NH; ++k) {
                float phv = s->phi_s[k*NOUT + outc];
#pragma unroll
                for (int r = 0; r < 4; ++r) {
                    float hv = *(const float*)&s->hdup[(bg*4 + r)*HS2 + k];
                    a4[r] = fmaf(hv, phv, a4[r]);
                }
            }
#pragma unroll
            for (int r = 0; r < 4; ++r)
                g_mu2[p][(((size_t)(b0 + bg*4 + r))*ND + d)*NOUT + outc] = a4[r];
        }
        {
            const float* hrow = (const float*)&s->hdup[bb_*HS2];
            float a = 0.f;
#pragma unroll
            for (int kk = 0; kk < 16; ++kk) {
                int k = seg*16 + kk;
                a = fmaf(hrow[2*k], s->fbw_s[k], a);
            }
            a += __shfl_xor_sync(0xffffffffu, a, 1);
            a += __shfl_xor_sync(0xffffffffu, a, 2);
            a += __shfl_xor_sync(0xffffffffu, a, 4);
            if (seg == 0)
                g_bt2[p][(size_t)(b0 + bb_)*ND + d] = __expf(tanhfast(a + btg));
        }
        __threadfence();
        grid_bar();
#pragma unroll
        for (int rr = 0; rr < 4; ++rr) {
            int b = w*4 + rr;
            float bt = g_bt2[p][(size_t)(b0 + b)*ND + lane];
            float ssum = bt;
#pragma unroll
            for (int o = 16; o > 0; o >>= 1)
                ssum += __shfl_xor_sync(0xffffffffu, ssum, o);
            float beta = __fdividef(bt, ssum);
            if (d == 0)
                out[B_OFS + ((size_t)(b0 + b)*NF + f)*ND + lane] = beta;
            float y = 0.f;
            const float* mup = g_mu2[p] + ((size_t)(b0 + b)*ND)*NOUT + lane;
#pragma unroll
            for (int d2 = 0; d2 < ND; ++d2)
                y = fmaf(__shfl_sync(0xffffffffu, beta, d2), mup[d2*NOUT], y);
            if (d == 0)
                out[((size_t)(b0 + b)*NF + f)*NOUT + lane] = y;
            float pr = y * proj_w[lane*ND + d];
#pragma unroll
            for (int o = 16; o > 0; o >>= 1)
                pr += __shfl_xor_sync(0xffffffffu, pr, o);
            if (lane == 0) s->xs[b] = pr + proj_b[d];
        }
        if (f == NF - 1) break;

        cell_pipe(s, wt0, wt1, gw, q, g, lane, c0, c, h2, f < NF - 2);
#pragma unroll
        for (int cc = 0; cc < 8; ++cc) {
            s->hdup[lane*HS2 + c0 + cc]      = dup2(h2[cc]);
            s->hdup[(lane+32)*HS2 + c0 + cc] = dup2(h2[8 + cc]);
        }
        __syncthreads();
    }
}

// ==== launch ====
extern "C" void kernel_launch(void* const* d_in, const int* in_sizes, int n_in,
                              void* d_out, int out_size) {
    const float* x   = (const float*)d_in[0];
    const float* Uj  = (const float*)d_in[1];
    const float* Ui  = (const float*)d_in[2];
    const float* Uf  = (const float*)d_in[3];
    const float* Uo  = (const float*)d_in[4];
    const float* Wj  = (const float*)d_in[5];
    const float* Wi  = (const float*)d_in[6];
    const float* Wf  = (const float*)d_in[7];
    const float* Wo  = (const float*)d_in[8];
    const float* bj  = (const float*)d_in[9];
    const float* bi  = (const float*)d_in[10];
    const float* bf  = (const float*)d_in[11];
    const float* bo  = (const float*)d_in[12];
    const float* Fa  = (const float*)d_in[13];
    const float* Fab = (const float*)d_in[14];
    const float* Fbw = (const float*)d_in[15];
    const float* Fbb = (const float*)d_in[16];
    const float* Phw = (const float*)d_in[17];
    const float* Phb = (const float*)d_in[18];
    const float* prw = (const float*)d_in[19];
    const float* prb = (const float*)d_in[20];
    float* out = (float*)d_out;

    int smE = (int)sizeof(SEnc);
    int smF = (int)sizeof(SF);
    cudaFuncSetAttribute(enc_kernel, cudaFuncAttributeMaxDynamicSharedMemorySize, smE);
    cudaFuncSetAttribute(fc_kernel,  cudaFuncAttributeMaxDynamicSharedMemorySize, smF);

    prep_kernel<<<4096, 256>>>(Wj, Wi, Wf, Wo);
    enc_kernel<<<NCTA, NTHR, smE>>>(x, Uj,Ui,Uf,Uo, bj,bi,bf,bo,
                                    Fa, Fab, Phw, Phb, Fbw, out);
    alphas_fin_kernel<<<(A_CNT + 255)/256, 256>>>(out);
    fc_kernel<<<NCTA, NTHR, smF>>>(Uj,Ui,Uf,Uo, Wj,Wi,Wf,Wo, bj,bi,bf,bo,
                                   Phw, Fbw, Fbb, prw, prb, out);
}

// round 16
// speedup vs baseline: 1.2972x; 1.1294x over previous
#include <cuda_runtime.h>
#include <cuda_fp16.h>

#define NB 256
#define NT 96
#define ND 32
#define NOUT 32
#define NH 128
#define NF 24
#define BC 64
#define NCTA 128
#define NTHR 512
#define HS2 129
#define GST 130

#define F_CNT (NB*NF*NOUT)
#define A_OFS F_CNT
#define A_CNT (NB*NT*ND)
#define B_OFS (A_OFS + A_CNT)
#define O_OFS (B_OFS + NB*NF*ND)

typedef unsigned long long ull;

__device__ float g_h[ND*NB*NH];
__device__ float g_c[ND*NB*NH];
__device__ float g_den[NB*ND];
__device__ float g_mug[NB*ND*NOUT];
__device__ float g_btg[NB*ND];
__device__ float g_mu2[2][NB*ND*NOUT];
__device__ float g_bt2[2][NB*ND];
__device__ unsigned g_cnt;
__device__ unsigned g_gen;
__device__ __half g_Wimg[4*32*16384];  // W^T fp16 swizzled images (4MB)

// ---- helpers ----
__device__ __forceinline__ ull pack2(float lo, float hi) {
    ull r; asm("mov.b64 %0, {%1, %2};" : "=l"(r)
        : "r"(__float_as_uint(lo)), "r"(__float_as_uint(hi)));
    return r;
}
__device__ __forceinline__ ull dup2(float v) {
    ull r; unsigned u = __float_as_uint(v);
    asm("mov.b64 %0, {%1, %1};" : "=l"(r) : "r"(u));
    return r;
}
__device__ __forceinline__ void unpack2(ull p, float &lo, float &hi) {
    unsigned a, b;
    asm("mov.b64 {%0, %1}, %2;" : "=r"(a), "=r"(b) : "l"(p));
    lo = __uint_as_float(a); hi = __uint_as_float(b);
}
__device__ __forceinline__ void fma2(ull &acc, ull a, ull b) {
    asm("fma.rn.f32x2 %0, %1, %2, %0;" : "+l"(acc) : "l"(a), "l"(b));
}
__device__ __forceinline__ float sigf(float x) { return __fdividef(1.f, 1.f + __expf(-x)); }
__device__ __forceinline__ float tanhfast(float x) {
    float e = __expf(-2.f * x);
    return __fdividef(1.f - e, 1.f + e);
}
__device__ __forceinline__ void cp16(unsigned dst, const void* src) {
    asm volatile("cp.async.cg.shared.global [%0], [%1], 16;" :: "r"(dst), "l"(src));
}
__device__ __forceinline__ void cp_commit() { asm volatile("cp.async.commit_group;"); }
template<int N> __device__ __forceinline__ void cp_wait() {
    asm volatile("cp.async.wait_group %0;" :: "n"(N));
}
__device__ __forceinline__ unsigned sptr(const void* p) {
    return (unsigned)__cvta_generic_to_shared(p);
}
#define LDX4(r, a) asm volatile("ldmatrix.sync.aligned.m8n8.x4.shared.b16 {%0,%1,%2,%3},[%4];" \
    : "=r"((r)[0]),"=r"((r)[1]),"=r"((r)[2]),"=r"((r)[3]) : "r"(a))
#define MMAH(dd, a, b0v, b1v) asm volatile( \
    "mma.sync.aligned.m16n8k16.row.col.f32.f16.f16.f32 {%0,%1,%2,%3},{%4,%5,%6,%7},{%8,%9},{%0,%1,%2,%3};" \
    : "+f"((dd)[0]),"+f"((dd)[1]),"+f"((dd)[2]),"+f"((dd)[3]) \
    : "r"((a)[0]),"r"((a)[1]),"r"((a)[2]),"r"((a)[3]),"r"(b0v),"r"(b1v))

__device__ __forceinline__ void splitf16(float a, float b, unsigned &hi, unsigned &lo) {
    __half ah = __float2half_rn(a), bh = __float2half_rn(b);
    __half al2 = __float2half_rn(a - __half2float(ah));
    __half bl2 = __float2half_rn(b - __half2float(bh));
    hi = (unsigned)*(unsigned short*)&ah | ((unsigned)*(unsigned short*)&bh << 16);
    lo = (unsigned)*(unsigned short*)&al2 | ((unsigned)*(unsigned short*)&bl2 << 16);
}

// ==== prep: W^T fp16 swizzled images. img[n][k] = fp16(W[k][n]). ====
__global__ void prep_kernel(const float* __restrict__ Wj, const float* __restrict__ Wi,
                            const float* __restrict__ Wf, const float* __restrict__ Wo) {
    int idx = blockIdx.x*256 + threadIdx.x;
    if (idx >= 4*32*128*64) return;
    int i2 = idx & 63, n = (idx>>6)&127, dd = (idx>>13)&31, g = idx>>18;
    const float* W = (g==0?Wj:g==1?Wi:g==2?Wf:Wo) + (size_t)dd*NH*NH;
    int k = 2*i2;
    __half h0 = __float2half_rn(W[k*NH + n]);
    __half h1 = __float2half_rn(W[(k+1)*NH + n]);
    unsigned hv = (unsigned)*(unsigned short*)&h0 | ((unsigned)*(unsigned short*)&h1 << 16);
    unsigned off = (unsigned)(n*128 + (((k>>3) ^ (n&7))<<3) + (k&7));
    __half* base = g_Wimg + ((size_t)g*32 + dd)*16384;
    *(unsigned*)((char*)base + off*2) = hv;
}

// ==== encoder: W fully resident, fp16 2-term ====
struct SEnc {
    __half Wres[4*16384];     // 128KB resident (reused as float gs staging at end)
    __half Ahi[8192], Alo[8192];  // 2 x 16KB
    float ub[1024];
    float part[BC*5];
    float xs[BC], es[BC], den_s[BC];
};

__global__ void __launch_bounds__(NTHR, 1) enc_kernel(
    const float* __restrict__ x,
    const float* __restrict__ Uj, const float* __restrict__ Ui,
    const float* __restrict__ Uf, const float* __restrict__ Uo,
    const float* __restrict__ bj, const float* __restrict__ bi_,
    const float* __restrict__ bf, const float* __restrict__ bo,
    const float* __restrict__ Fa, const float* __restrict__ Fab,
    const float* __restrict__ Phi_w, const float* __restrict__ Phi_b,
    const float* __restrict__ Fbw, float* __restrict__ out)
{
    extern __shared__ char smraw[];
    SEnc* s = (SEnc*)smraw;
    const int tid = threadIdx.x;
    const int d = blockIdx.x >> 2;
    const int b0 = (blockIdx.x & 3)*BC;
    const int lane = tid & 31, w = tid >> 5;
    const int rg = w & 3, gq = w >> 2;
    const int t4 = lane & 3;
    const int R = rg*16 + (lane >> 2);
    const int l8 = lane & 7, m = lane >> 3;
    const int rowA = rg*16 + ((m & 1) << 3) + l8; const int jA = (m >> 1) & 1;
    const int rowB0 = gq*32 + ((m >> 1) << 3) + l8; const int jB = m & 1;
    const int rowB1 = rowB0 + 16;
    const float fab = Fab[d];
    unsigned aHiB = sptr(s->Ahi), aLoB = sptr(s->Alo), wresB = sptr(s->Wres);

    // load W resident (once): 4 gates x 32KB
#pragma unroll
    for (int gi = 0; gi < 4; ++gi) {
        const char* src = (const char*)(g_Wimg + ((size_t)gi*32 + d)*16384) + tid*16;
        unsigned dst = wresB + (unsigned)gi*32768u + (unsigned)tid*16u;
#pragma unroll
        for (int j = 0; j < 4; ++j) cp16(dst + j*8192u, src + j*8192);
    }
    cp_commit();

    if (tid < 4*NH) {
        int gate = tid >> 7, k = tid & 127;
        const float* Up = gate==0?Uj:gate==1?Ui:gate==2?Uf:Uo;
        const float* Bp = gate==0?bj:gate==1?bi_:gate==2?bf:bo;
        s->ub[gate*256 + k] = Up[d*NH + k];
        s->ub[gate*256 + 128 + k] = Bp[d*NH + k];
    }
    if (tid < BC) s->den_s[tid] = 0.f;
    for (int i = tid; i < 8192; i += NTHR) {
        s->Ahi[i] = __half(0.f);
        s->Alo[i] = __half(0.f);
    }
    float fa0[4], fa1[4];
#pragma unroll
    for (int nb = 0; nb < 4; ++nb) {
        int col = gq*32 + nb*8 + t4*2;
        fa0[nb] = Fa[(size_t)d*NH + col];
        fa1[nb] = Fa[(size_t)d*NH + col + 1];
    }
    float c[16], h2[16], num[16];
#pragma unroll
    for (int i = 0; i < 16; ++i) { c[i] = 0.f; num[i] = 0.f; }
    cp_wait<0>();
    __syncthreads();

    for (int t = 0; t < NT; ++t) {
        if (tid < BC) s->xs[tid] = x[((size_t)(b0 + tid)*NT + t)*ND + d];
        __syncthreads();   // xs + A-tiles visible

        // gate loop: no syncs, W resident
#pragma unroll
        for (int g = 0; g < 4; ++g) {
            float acc[16];
            {
                float x0 = s->xs[R], x1 = s->xs[R + 8];
                const float* up = s->ub + g*256;
#pragma unroll
                for (int nb = 0; nb < 4; ++nb) {
                    int c0 = gq*32 + nb*8 + t4*2;
                    acc[nb*4+0] = fmaf(x0, up[c0],   up[128 + c0]);
                    acc[nb*4+1] = fmaf(x0, up[c0+1], up[128 + c0 + 1]);
                    acc[nb*4+2] = fmaf(x1, up[c0],   up[128 + c0]);
                    acc[nb*4+3] = fmaf(x1, up[c0+1], up[128 + c0 + 1]);
                }
            }
            unsigned wbg = wresB + (unsigned)g*32768u;
#pragma unroll
            for (int kb = 0; kb < 8; ++kb) {
                unsigned ah[4], al[4], bh[8];
                unsigned ao  = (unsigned)(rowA*256  + (((2*kb + jA) ^ (rowA  & 7)) << 4));
                unsigned bo0 = (unsigned)(rowB0*256 + (((2*kb + jB) ^ (rowB0 & 7)) << 4));
                unsigned bo1 = (unsigned)(rowB1*256 + (((2*kb + jB) ^ (rowB1 & 7)) << 4));
                LDX4(ah, aHiB + ao);
                LDX4(al, aLoB + ao);
                LDX4(bh + 0, wbg + bo0); LDX4(bh + 4, wbg + bo1);
                MMAH(acc+0,  ah, bh[0], bh[1]); MMAH(acc+0,  al, bh[0], bh[1]);
                MMAH(acc+4,  ah, bh[2], bh[3]); MMAH(acc+4,  al, bh[2], bh[3]);
                MMAH(acc+8,  ah, bh[4], bh[5]); MMAH(acc+8,  al, bh[4], bh[5]);
                MMAH(acc+12, ah, bh[6], bh[7]); MMAH(acc+12, al, bh[6], bh[7]);
            }
            if (g == 0) {
#pragma unroll
                for (int e = 0; e < 16; ++e) h2[e] = tanhfast(acc[e]);
            } else if (g == 1) {
#pragma unroll
                for (int e = 0; e < 16; ++e) h2[e] *= sigf(acc[e]);
            } else if (g == 2) {
#pragma unroll
                for (int e = 0; e < 16; ++e) c[e] = fmaf(c[e], sigf(acc[e]), h2[e]);
            } else {
#pragma unroll
                for (int e = 0; e < 16; ++e) h2[e] = sigf(acc[e]) * tanhfast(c[e]);
            }
        }
        __syncthreads();   // all warps done reading A tiles

        // ---- epilogue ----
        {
            size_t o0 = O_OFS + (((size_t)(b0 + R)*NT + t)*ND + d)*NH;
            size_t o1 = O_OFS + (((size_t)(b0 + R + 8)*NT + t)*ND + d)*NH;
            char* ahp = (char*)s->Ahi; char* alp = (char*)s->Alo;
            float p0 = 0.f, p1 = 0.f;
#pragma unroll
            for (int nb = 0; nb < 4; ++nb) {
                int col = gq*32 + nb*8 + t4*2;
                float h00 = h2[nb*4+0], h01 = h2[nb*4+1];
                float h10 = h2[nb*4+2], h11 = h2[nb*4+3];
                *(float2*)(out + o0 + col) = make_float2(h00, h01);
                *(float2*)(out + o1 + col) = make_float2(h10, h11);
                p0 = fmaf(h00, fa0[nb], fmaf(h01, fa1[nb], p0));
                p1 = fmaf(h10, fa0[nb], fmaf(h11, fa1[nb], p1));
                unsigned sw0 = (unsigned)(R*256 + (((col>>3) ^ (R & 7)) << 4) + t4*4);
                unsigned sw1 = (unsigned)((R+8)*256 + (((col>>3) ^ ((R+8) & 7)) << 4) + t4*4);
                unsigned hv, lv;
                splitf16(h00, h01, hv, lv);
                *(unsigned*)(ahp + sw0) = hv; *(unsigned*)(alp + sw0) = lv;
                splitf16(h10, h11, hv, lv);
                *(unsigned*)(ahp + sw1) = hv; *(unsigned*)(alp + sw1) = lv;
            }
            p0 += __shfl_xor_sync(0xffffffffu, p0, 1);
            p0 += __shfl_xor_sync(0xffffffffu, p0, 2);
            p1 += __shfl_xor_sync(0xffffffffu, p1, 1);
            p1 += __shfl_xor_sync(0xffffffffu, p1, 2);
            if (t4 == 0) { s->part[R*5 + gq] = p0; s->part[(R+8)*5 + gq] = p1; }
        }
        __syncthreads();
        if (tid < 256) {
            int r2 = tid >> 2, q = tid & 3;
            float v = s->part[r2*5 + q];
            v += __shfl_xor_sync(0xffffffffu, v, 1);
            v += __shfl_xor_sync(0xffffffffu, v, 2);
            if (q == 0) {
                float e = __expf(tanhfast(v + fab));
                s->es[r2] = e;
                s->den_s[r2] += e;
                out[A_OFS + ((size_t)(b0 + r2)*NT + t)*ND + d] = e;
            }
        }
        __syncthreads();
        {
            float e0 = s->es[R], e1 = s->es[R + 8];
#pragma unroll
            for (int nb = 0; nb < 4; ++nb) {
                num[nb*4+0] = fmaf(e0, h2[nb*4+0], num[nb*4+0]);
                num[nb*4+1] = fmaf(e0, h2[nb*4+1], num[nb*4+1]);
                num[nb*4+2] = fmaf(e1, h2[nb*4+2], num[nb*4+2]);
                num[nb*4+3] = fmaf(e1, h2[nb*4+3], num[nb*4+3]);
            }
        }
    }

    // ---- handoff (gs staged in Wres region) ----
    float* gs = (float*)s->Wres;
    {
        float inv0 = __fdividef(1.f, s->den_s[R]);
        float inv1 = __fdividef(1.f, s->den_s[R + 8]);
        size_t g0o = ((size_t)d*NB + b0 + R)*NH;
        size_t g1o = ((size_t)d*NB + b0 + R + 8)*NH;
#pragma unroll
        for (int nb = 0; nb < 4; ++nb) {
            int col = gq*32 + nb*8 + t4*2;
            *(float2*)(g_h + g0o + col) = make_float2(h2[nb*4+0], h2[nb*4+1]);
            *(float2*)(g_h + g1o + col) = make_float2(h2[nb*4+2], h2[nb*4+3]);
            *(float2*)(g_c + g0o + col) = make_float2(c[nb*4+0], c[nb*4+1]);
            *(float2*)(g_c + g1o + col) = make_float2(c[nb*4+2], c[nb*4+3]);
            gs[R*GST + col]         = num[nb*4+0]*inv0;
            gs[R*GST + col + 1]     = num[nb*4+1]*inv0;
            gs[(R+8)*GST + col]     = num[nb*4+2]*inv1;
            gs[(R+8)*GST + col + 1] = num[nb*4+3]*inv1;
        }
    }
    if (tid < BC) g_den[(size_t)(b0 + tid)*ND + d] = s->den_s[tid];
    __syncthreads();
    {   // mu_g
        int outc = tid & 31, bg = tid >> 5;
        float a4[4];
        float pb = Phi_b[outc];
#pragma unroll
        for (int r = 0; r < 4; ++r) a4[r] = pb;
#pragma unroll 2
        for (int k = 0; k < NH; ++k) {
            float pg = Phi_w[k*NOUT + outc];
#pragma unroll
            for (int r = 0; r < 4; ++r)
                a4[r] = fmaf(gs[(bg*4 + r)*GST + k], pg, a4[r]);
        }
#pragma unroll
        for (int r = 0; r < 4; ++r)
            g_mug[(((size_t)(b0 + bg*4 + r))*ND + d)*NOUT + outc] = a4[r];
    }
    {   // bt_g
        int b = tid >> 3, seg = tid & 7;
        float a = 0.f;
#pragma unroll
        for (int kk = 0; kk < 16; ++kk) {
            int k = seg*16 + kk;
            a = fmaf(gs[b*GST + k], Fbw[k], a);
        }
        a += __shfl_xor_sync(0xffffffffu, a, 1);
        a += __shfl_xor_sync(0xffffffffu, a, 2);
        a += __shfl_xor_sync(0xffffffffu, a, 4);
        if (seg == 0) g_btg[(size_t)(b0 + b)*ND + d] = a;
    }
}

// ==== alphas finalize ====
__global__ void alphas_fin_kernel(float* __restrict__ out) {
    int i = blockIdx.x*256 + threadIdx.x;
    if (i >= A_CNT) return;
    int b = i / (NT*ND), d = i & (ND-1);
    out[A_OFS + i] = __fdividef(out[A_OFS + i], g_den[(size_t)b*ND + d]);
}

// ==== fc (scalar champion, verbatim) ====
struct SF {
    float Wt[2][4*32*128];
    ull   hdup[BC*HS2];
    float phi_s[NH*NOUT];
    float fbw_s[NH];
    float ub[4*2*NH];
    float xs[BC];
};

__device__ __forceinline__ void issue_tile(unsigned wtb, const float* __restrict__ gw,
                                           int tile, int q, int g) {
    unsigned dst = wtb + (unsigned)(g*4096 + q*4)*4u;
    const float4* src = (const float4*)(gw + tile*4096) + q;
#pragma unroll
    for (int j = 0; j < 8; ++j) cp16(dst + j*2048u, src + j*128);
    cp_commit();
}
__device__ __forceinline__ void compute_tile(const float* __restrict__ wt,
                                             const ull* __restrict__ h0p,
                                             const ull* __restrict__ h1p,
                                             int c0, ull* acc) {
    const float* base = wt + c0;
    ulonglong2 wa = *(const ulonglong2*)(base);
    ulonglong2 wb = *(const ulonglong2*)(base + 4);
    ull h0 = h0p[0], h1 = h1p[0];
#pragma unroll 4
    for (int kk = 0; kk < 32; ++kk) {
        ull h0n = h0p[kk+1], h1n = h1p[kk+1];
#pragma unroll
        for (int g = 0; g < 4; ++g) {
            const float* nb = base + (g == 3 ? (kk+1)*128 : (g+1)*4096 + kk*128);
            ulonglong2 wan = *(const ulonglong2*)(nb);
            ulonglong2 wbn = *(const ulonglong2*)(nb + 4);
            fma2(acc[g*8+0], h0, wa.x); fma2(acc[g*8+1], h0, wa.y);
            fma2(acc[g*8+2], h0, wb.x); fma2(acc[g*8+3], h0, wb.y);
            fma2(acc[g*8+4], h1, wa.x); fma2(acc[g*8+5], h1, wa.y);
            fma2(acc[g*8+6], h1, wb.x); fma2(acc[g*8+7], h1, wb.y);
            wa = wan; wb = wbn;
        }
        h0 = h0n; h1 = h1n;
    }
}
#define INITG(gg) { \
    const float* up = s->ub + (gg)*256 + c0; \
    float4 u0 = *(const float4*)(up);       float4 u1 = *(const float4*)(up + 4); \
    float4 v0 = *(const float4*)(up + 128); float4 v1 = *(const float4*)(up + 132); \
    acc[(gg)*8+0] = pack2(fmaf(xv0,u0.x,v0.x), fmaf(xv0,u0.y,v0.y)); \
    acc[(gg)*8+1] = pack2(fmaf(xv0,u0.z,v0.z), fmaf(xv0,u0.w,v0.w)); \
    acc[(gg)*8+2] = pack2(fmaf(xv0,u1.x,v1.x), fmaf(xv0,u1.y,v1.y)); \
    acc[(gg)*8+3] = pack2(fmaf(xv0,u1.z,v1.z), fmaf(xv0,u1.w,v1.w)); \
    acc[(gg)*8+4] = pack2(fmaf(xv1,u0.x,v0.x), fmaf(xv1,u0.y,v0.y)); \
    acc[(gg)*8+5] = pack2(fmaf(xv1,u0.z,v0.z), fmaf(xv1,u0.w,v0.w)); \
    acc[(gg)*8+6] = pack2(fmaf(xv1,u1.x,v1.x), fmaf(xv1,u1.y,v1.y)); \
    acc[(gg)*8+7] = pack2(fmaf(xv1,u1.z,v1.z), fmaf(xv1,u1.w,v1.w)); }

__device__ __forceinline__ void cell_pipe(
    SF* s, unsigned wt0, unsigned wt1,
    const float* __restrict__ gw, int q, int g,
    int lane, int c0, float* c, float* h2, bool pf)
{
    ull acc[32];
    __syncthreads();
    {
        float xv0 = s->xs[lane], xv1 = s->xs[lane + 32];
        INITG(0); INITG(1); INITG(2); INITG(3);
    }
    const ull* h0b = s->hdup + (size_t)lane*HS2;
    const ull* h1b = s->hdup + (size_t)(lane + 32)*HS2;
#pragma unroll 1
    for (int t = 0; t < 4; ++t) {
        if (t < 3 || pf) cp_wait<1>(); else cp_wait<0>();
        __syncthreads();
        const float* wt = (t & 1) ? (const float*)(s->Wt[1]) : (const float*)(s->Wt[0]);
        compute_tile(wt, h0b + t*32, h1b + t*32, c0, acc);
        __syncthreads();
        if (t < 2 || pf) issue_tile((t & 1) ? wt1 : wt0, gw, (t + 2) & 3, q, g);
    }
#pragma unroll
    for (int e = 0; e < 8; ++e) {
        int ii = (e >> 2)*8 + (e & 3)*2;
        float jl, jh, il, ih, fl, fh, ol, oh;
        unpack2(acc[e], jl, jh);
        unpack2(acc[8+e], il, ih);
        unpack2(acc[16+e], fl, fh);
        unpack2(acc[24+e], ol, oh);
        float cl = fmaf(c[ii],   sigf(fl), sigf(il)*tanhfast(jl));
        float ch = fmaf(c[ii+1], sigf(fh), sigf(ih)*tanhfast(jh));
        c[ii] = cl; c[ii+1] = ch;
        h2[ii]   = sigf(ol)*tanhfast(cl);
        h2[ii+1] = sigf(oh)*tanhfast(ch);
    }
}
__device__ __forceinline__ void grid_bar() {
    __syncthreads();
    if (threadIdx.x == 0) {
        __threadfence();
        unsigned gen = *(volatile unsigned*)&g_gen;
        if (atomicAdd(&g_cnt, 1u) == NCTA - 1u) {
            g_cnt = 0u; __threadfence(); atomicAdd(&g_gen, 1u);
        } else {
            while (*(volatile unsigned*)&g_gen == gen) __nanosleep(64);
        }
        __threadfence();
    }
    __syncthreads();
}

__global__ void __launch_bounds__(NTHR, 1) fc_kernel(
    const float* __restrict__ Uj, const float* __restrict__ Ui,
    const float* __restrict__ Uf, const float* __restrict__ Uo,
    const float* __restrict__ Wj, const float* __restrict__ Wi,
    const float* __restrict__ Wf, const float* __restrict__ Wo,
    const float* __restrict__ bj, const float* __restrict__ bi_,
    const float* __restrict__ bf, const float* __restrict__ bo,
    const float* __restrict__ Phi_w, const float* __restrict__ Fbw,
    const float* __restrict__ Fbb,
    const float* __restrict__ proj_w, const float* __restrict__ proj_b,
    float* __restrict__ out)
{
    extern __shared__ char smem_raw[];
    SF* s = (SF*)smem_raw;
    const int tid = threadIdx.x;
    const int d = blockIdx.x >> 2;
    const int b0 = (blockIdx.x & 3)*BC;
    const int lane = tid & 31, w = tid >> 5;
    const int c0 = w*8, q = tid & 127, g = tid >> 7;
    const int outc = tid & 31, bg = tid >> 5;
    const int bb_ = tid >> 3, seg = tid & 7;

    const size_t dHH = (size_t)d*NH*NH;
    const float* gw = (g==0?Wj:g==1?Wi:g==2?Wf:Wo) + dHH;
    unsigned wt0 = sptr(s->Wt[0]), wt1 = sptr(s->Wt[1]);

    issue_tile(wt0, gw, 0, q, g);
    issue_tile(wt1, gw, 1, q, g);

    for (int i = tid; i < BC*NH; i += NTHR) {
        int b = i >> 7, k = i & 127;
        s->hdup[b*HS2 + k] = dup2(g_h[((size_t)d*NB + b0 + b)*NH + k]);
    }
    for (int i = tid; i < NH*NOUT; i += NTHR)
        s->phi_s[i] = Phi_w[(NH + (i >> 5))*NOUT + (i & 31)];
    if (tid < NH) s->fbw_s[tid] = Fbw[NH + tid];
    if (tid < 4*NH) {
        int gate = tid >> 7, k = tid & 127;
        const float* Up = gate==0?Uj:gate==1?Ui:gate==2?Uf:Uo;
        const float* Bp = gate==0?bj:gate==1?bi_:gate==2?bf:bo;
        s->ub[gate*256 + k] = Up[d*NH + k];
        s->ub[gate*256 + 128 + k] = Bp[d*NH + k];
    }

    float c[16], h2[16];
    {
        size_t g0 = ((size_t)d*NB + b0 + lane)*NH + c0;
        size_t g1 = ((size_t)d*NB + b0 + lane + 32)*NH + c0;
        float4 a0 = *(const float4*)(g_c + g0);
        float4 a1 = *(const float4*)(g_c + g0 + 4);
        float4 a2 = *(const float4*)(g_c + g1);
        float4 a3 = *(const float4*)(g_c + g1 + 4);
        c[0]=a0.x;c[1]=a0.y;c[2]=a0.z;c[3]=a0.w;
        c[4]=a1.x;c[5]=a1.y;c[6]=a1.z;c[7]=a1.w;
        c[8]=a2.x;c[9]=a2.y;c[10]=a2.z;c[11]=a2.w;
        c[12]=a3.x;c[13]=a3.y;c[14]=a3.z;c[15]=a3.w;
    }
    float mug[4];
#pragma unroll
    for (int r = 0; r < 4; ++r)
        mug[r] = g_mug[(((size_t)(b0 + bg*4 + r))*ND + d)*NOUT + outc];
    const float btg = g_btg[(size_t)(b0 + bb_)*ND + d] + Fbb[0];
    __syncthreads();

    for (int f = 0; f < NF; ++f) {
        const int p = f & 1;
        {
            float a4[4];
#pragma unroll
            for (int r = 0; r < 4; ++r) a4[r] = mug[r];
#pragma unroll 2
            for (int k = 0; k < NH; ++k) {
                float phv = s->phi_s[k*NOUT + outc];
#pragma unroll
                for (int r = 0; r < 4; ++r) {
                    float hv = *(const float*)&s->hdup[(bg*4 + r)*HS2 + k];
                    a4[r] = fmaf(hv, phv, a4[r]);
                }
            }
#pragma unroll
            for (int r = 0; r < 4; ++r)
                g_mu2[p][(((size_t)(b0 + bg*4 + r))*ND + d)*NOUT + outc] = a4[r];
        }
        {
            const float* hrow = (const float*)&s->hdup[bb_*HS2];
            float a = 0.f;
#pragma unroll
            for (int kk = 0; kk < 16; ++kk) {
                int k = seg*16 + kk;
                a = fmaf(hrow[2*k], s->fbw_s[k], a);
            }
            a += __shfl_xor_sync(0xffffffffu, a, 1);
            a += __shfl_xor_sync(0xffffffffu, a, 2);
            a += __shfl_xor_sync(0xffffffffu, a, 4);
            if (seg == 0)
                g_bt2[p][(size_t)(b0 + bb_)*ND + d] = __expf(tanhfast(a + btg));
        }
        __threadfence();
        grid_bar();
#pragma unroll
        for (int rr = 0; rr < 4; ++rr) {
            int b = w*4 + rr;
            float bt = g_bt2[p][(size_t)(b0 + b)*ND + lane];
            float ssum = bt;
#pragma unroll
            for (int o = 16; o > 0; o >>= 1)
                ssum += __shfl_xor_sync(0xffffffffu, ssum, o);
            float beta = __fdividef(bt, ssum);
            if (d == 0)
                out[B_OFS + ((size_t)(b0 + b)*NF + f)*ND + lane] = beta;
            float y = 0.f;
            const float* mup = g_mu2[p] + ((size_t)(b0 + b)*ND)*NOUT + lane;
#pragma unroll
            for (int d2 = 0; d2 < ND; ++d2)
                y = fmaf(__shfl_sync(0xffffffffu, beta, d2), mup[d2*NOUT], y);
            if (d == 0)
                out[((size_t)(b0 + b)*NF + f)*NOUT + lane] = y;
            float pr = y * proj_w[lane*ND + d];
#pragma unroll
            for (int o = 16; o > 0; o >>= 1)
                pr += __shfl_xor_sync(0xffffffffu, pr, o);
            if (lane == 0) s->xs[b] = pr + proj_b[d];
        }
        if (f == NF - 1) break;

        cell_pipe(s, wt0, wt1, gw, q, g, lane, c0, c, h2, f < NF - 2);
#pragma unroll
        for (int cc = 0; cc < 8; ++cc) {
            s->hdup[lane*HS2 + c0 + cc]      = dup2(h2[cc]);
            s->hdup[(lane+32)*HS2 + c0 + cc] = dup2(h2[8 + cc]);
        }
        __syncthreads();
    }
}

// ==== launch ====
extern "C" void kernel_launch(void* const* d_in, const int* in_sizes, int n_in,
                              void* d_out, int out_size) {
    const float* x   = (const float*)d_in[0];
    const float* Uj  = (const float*)d_in[1];
    const float* Ui  = (const float*)d_in[2];
    const float* Uf  = (const float*)d_in[3];
    const float* Uo  = (const float*)d_in[4];
    const float* Wj  = (const float*)d_in[5];
    const float* Wi  = (const float*)d_in[6];
    const float* Wf  = (const float*)d_in[7];
    const float* Wo  = (const float*)d_in[8];
    const float* bj  = (const float*)d_in[9];
    const float* bi  = (const float*)d_in[10];
    const float* bf  = (const float*)d_in[11];
    const float* bo  = (const float*)d_in[12];
    const float* Fa  = (const float*)d_in[13];
    const float* Fab = (const float*)d_in[14];
    const float* Fbw = (const float*)d_in[15];
    const float* Fbb = (const float*)d_in[16];
    const float* Phw = (const float*)d_in[17];
    const float* Phb = (const float*)d_in[18];
    const float* prw = (const float*)d_in[19];
    const float* prb = (const float*)d_in[20];
    float* out = (float*)d_out;

    int smE = (int)sizeof(SEnc);
    int smF = (int)sizeof(SF);
    cudaFuncSetAttribute(enc_kernel, cudaFuncAttributeMaxDynamicSharedMemorySize, smE);
    cudaFuncSetAttribute(fc_kernel,  cudaFuncAttributeMaxDynamicSharedMemorySize, smF);

    prep_kernel<<<4096, 256>>>(Wj, Wi, Wf, Wo);
    enc_kernel<<<NCTA, NTHR, smE>>>(x, Uj,Ui,Uf,Uo, bj,bi,bf,bo,
                                    Fa, Fab, Phw, Phb, Fbw, out);
    alphas_fin_kernel<<<(A_CNT + 255)/256, 256>>>(out);
    fc_kernel<<<NCTA, NTHR, smF>>>(Uj,Ui,Uf,Uo, Wj,Wi,Wf,Wo, bj,bi,bf,bo,
                                   Phw, Fbw, Fbb, prw, prb, out);
}

// round 17
// speedup vs baseline: 2.1455x; 1.6540x over previous
#include <cuda_runtime.h>
#include <cuda_fp16.h>

#define NB 256
#define NT 96
#define ND 32
#define NOUT 32
#define NH 128
#define NF 24
#define BC 64
#define NCTA 128
#define NTHR 512
#define GST 130

#define F_CNT (NB*NF*NOUT)
#define A_OFS F_CNT
#define A_CNT (NB*NT*ND)
#define B_OFS (A_OFS + A_CNT)
#define O_OFS (B_OFS + NB*NF*ND)

typedef unsigned long long ull;

__device__ float g_h[ND*NB*NH];
__device__ float g_c[ND*NB*NH];
__device__ float g_den[NB*ND];
__device__ float g_mug[NB*ND*NOUT];
__device__ float g_btg[NB*ND];
__device__ float g_mu2[2][NB*ND*NOUT];
__device__ float g_bt2[2][NB*ND];
__device__ unsigned g_cnt;
__device__ unsigned g_gen;
__device__ __half g_Wimg[4*32*16384];  // W^T fp16 swizzled images (4MB)

// ---- helpers ----
__device__ __forceinline__ float tanha(float x) {
    float r; asm("tanh.approx.f32 %0, %1;" : "=f"(r) : "f"(x)); return r;
}
__device__ __forceinline__ float siga(float x) {
    return fmaf(0.5f, tanha(0.5f*x), 0.5f);
}
__device__ __forceinline__ void cp16(unsigned dst, const void* src) {
    asm volatile("cp.async.cg.shared.global [%0], [%1], 16;" :: "r"(dst), "l"(src));
}
__device__ __forceinline__ void cp_commit() { asm volatile("cp.async.commit_group;"); }
template<int N> __device__ __forceinline__ void cp_wait() {
    asm volatile("cp.async.wait_group %0;" :: "n"(N));
}
__device__ __forceinline__ unsigned sptr(const void* p) {
    return (unsigned)__cvta_generic_to_shared(p);
}
#define LDX4(r, a) asm volatile("ldmatrix.sync.aligned.m8n8.x4.shared.b16 {%0,%1,%2,%3},[%4];" \
    : "=r"((r)[0]),"=r"((r)[1]),"=r"((r)[2]),"=r"((r)[3]) : "r"(a))
#define MMAH(dd, a, b0v, b1v) asm volatile( \
    "mma.sync.aligned.m16n8k16.row.col.f32.f16.f16.f32 {%0,%1,%2,%3},{%4,%5,%6,%7},{%8,%9},{%0,%1,%2,%3};" \
    : "+f"((dd)[0]),"+f"((dd)[1]),"+f"((dd)[2]),"+f"((dd)[3]) \
    : "r"((a)[0]),"r"((a)[1]),"r"((a)[2]),"r"((a)[3]),"r"(b0v),"r"(b1v))

__device__ __forceinline__ void splitf16(float a, float b, unsigned &hi, unsigned &lo) {
    __half ah = __float2half_rn(a), bh = __float2half_rn(b);
    __half al2 = __float2half_rn(a - __half2float(ah));
    __half bl2 = __float2half_rn(b - __half2float(bh));
    hi = (unsigned)*(unsigned short*)&ah | ((unsigned)*(unsigned short*)&bh << 16);
    lo = (unsigned)*(unsigned short*)&al2 | ((unsigned)*(unsigned short*)&bl2 << 16);
}

// ==== prep: W^T fp16 swizzled images ====
__global__ void prep_kernel(const float* __restrict__ Wj, const float* __restrict__ Wi,
                            const float* __restrict__ Wf, const float* __restrict__ Wo) {
    int idx = blockIdx.x*256 + threadIdx.x;
    if (idx >= 4*32*128*64) return;
    int i2 = idx & 63, n = (idx>>6)&127, dd = (idx>>13)&31, g = idx>>18;
    const float* W = (g==0?Wj:g==1?Wi:g==2?Wf:Wo) + (size_t)dd*NH*NH;
    int k = 2*i2;
    __half h0 = __float2half_rn(W[k*NH + n]);
    __half h1 = __float2half_rn(W[(k+1)*NH + n]);
    unsigned hv = (unsigned)*(unsigned short*)&h0 | ((unsigned)*(unsigned short*)&h1 << 16);
    unsigned off = (unsigned)(n*128 + (((k>>3) ^ (n&7))<<3) + (k&7));
    __half* base = g_Wimg + ((size_t)g*32 + dd)*16384;
    *(unsigned*)((char*)base + off*2) = hv;
}

// ---- load resident W (4 x 32KB) ----
__device__ __forceinline__ void loadWres(unsigned wresB, int d, int tid) {
#pragma unroll
    for (int gi = 0; gi < 4; ++gi) {
        const char* src = (const char*)(g_Wimg + ((size_t)gi*32 + d)*16384) + tid*16;
        unsigned dst = wresB + (unsigned)gi*32768u + (unsigned)tid*16u;
#pragma unroll
        for (int j = 0; j < 4; ++j) cp16(dst + j*8192u, src + j*8192);
    }
    cp_commit();
}

// ---- U/b staging ----
#define STAGE_UB(ubarr) \
    if (tid < 4*NH) { \
        int gate = tid >> 7, k = tid & 127; \
        const float* Up = gate==0?Uj:gate==1?Ui:gate==2?Uf:Uo; \
        const float* Bp = gate==0?bj:gate==1?bi_:gate==2?bf:bo; \
        (ubarr)[gate*256 + k] = Up[d*NH + k]; \
        (ubarr)[gate*256 + 128 + k] = Bp[d*NH + k]; \
    }

// ---- shared HMMA LSTM cell: resident W, fp16 2-term, syncs included ----
__device__ __forceinline__ void cell_hmma(
    unsigned wresB, unsigned aHiB, unsigned aLoB,
    const float* __restrict__ ub, const float* __restrict__ xs,
    int lane, int w, float* c, float* h2)
{
    const int rg = w & 3, gq = w >> 2;
    const int t4 = lane & 3;
    const int R = rg*16 + (lane >> 2);
    const int l8 = lane & 7, m = lane >> 3;
    const int rowA = rg*16 + ((m & 1) << 3) + l8; const int jA = (m >> 1) & 1;
    const int rowB0 = gq*32 + ((m >> 1) << 3) + l8; const int jB = m & 1;
    const int rowB1 = rowB0 + 16;

    __syncthreads();   // xs + A tiles visible
#pragma unroll
    for (int g = 0; g < 4; ++g) {
        float acc[16];
        {
            float x0 = xs[R], x1 = xs[R + 8];
            const float* up = ub + g*256;
#pragma unroll
            for (int nb = 0; nb < 4; ++nb) {
                int c0 = gq*32 + nb*8 + t4*2;
                acc[nb*4+0] = fmaf(x0, up[c0],   up[128 + c0]);
                acc[nb*4+1] = fmaf(x0, up[c0+1], up[128 + c0 + 1]);
                acc[nb*4+2] = fmaf(x1, up[c0],   up[128 + c0]);
                acc[nb*4+3] = fmaf(x1, up[c0+1], up[128 + c0 + 1]);
            }
        }
        unsigned wbg = wresB + (unsigned)g*32768u;
#pragma unroll
        for (int kb = 0; kb < 8; ++kb) {
            unsigned ah[4], al[4], bh[8];
            unsigned ao  = (unsigned)(rowA*256  + (((2*kb + jA) ^ (rowA  & 7)) << 4));
            unsigned bo0 = (unsigned)(rowB0*256 + (((2*kb + jB) ^ (rowB0 & 7)) << 4));
            unsigned bo1 = (unsigned)(rowB1*256 + (((2*kb + jB) ^ (rowB1 & 7)) << 4));
            LDX4(ah, aHiB + ao);
            LDX4(al, aLoB + ao);
            LDX4(bh + 0, wbg + bo0); LDX4(bh + 4, wbg + bo1);
            MMAH(acc+0,  ah, bh[0], bh[1]); MMAH(acc+0,  al, bh[0], bh[1]);
            MMAH(acc+4,  ah, bh[2], bh[3]); MMAH(acc+4,  al, bh[2], bh[3]);
            MMAH(acc+8,  ah, bh[4], bh[5]); MMAH(acc+8,  al, bh[4], bh[5]);
            MMAH(acc+12, ah, bh[6], bh[7]); MMAH(acc+12, al, bh[6], bh[7]);
        }
        if (g == 0) {
#pragma unroll
            for (int e = 0; e < 16; ++e) h2[e] = tanha(acc[e]);
        } else if (g == 1) {
#pragma unroll
            for (int e = 0; e < 16; ++e) h2[e] *= siga(acc[e]);
        } else if (g == 2) {
#pragma unroll
            for (int e = 0; e < 16; ++e) c[e] = fmaf(c[e], siga(acc[e]), h2[e]);
        } else {
#pragma unroll
            for (int e = 0; e < 16; ++e) h2[e] = siga(acc[e]) * tanha(c[e]);
        }
    }
    __syncthreads();   // all warps done reading A tiles
}

// ==== encoder ====
struct SEnc {
    __half Wres[4*16384];         // 128KB resident (reused as float gs staging)
    __half Ahi[8192], Alo[8192];
    float ub[1024];
    float part[BC*5];
    float xs[BC], es[BC], den_s[BC];
};

__global__ void __launch_bounds__(NTHR, 1) enc_kernel(
    const float* __restrict__ x,
    const float* __restrict__ Uj, const float* __restrict__ Ui,
    const float* __restrict__ Uf, const float* __restrict__ Uo,
    const float* __restrict__ bj, const float* __restrict__ bi_,
    const float* __restrict__ bf, const float* __restrict__ bo,
    const float* __restrict__ Fa, const float* __restrict__ Fab,
    const float* __restrict__ Phi_w, const float* __restrict__ Phi_b,
    const float* __restrict__ Fbw, float* __restrict__ out)
{
    extern __shared__ char smraw[];
    SEnc* s = (SEnc*)smraw;
    const int tid = threadIdx.x;
    const int d = blockIdx.x >> 2;
    const int b0 = (blockIdx.x & 3)*BC;
    const int lane = tid & 31, w = tid >> 5;
    const int rg = w & 3, gq = w >> 2;
    const int t4 = lane & 3;
    const int R = rg*16 + (lane >> 2);
    const float fab = Fab[d];
    unsigned aHiB = sptr(s->Ahi), aLoB = sptr(s->Alo), wresB = sptr(s->Wres);

    loadWres(wresB, d, tid);
    STAGE_UB(s->ub);
    if (tid < BC) s->den_s[tid] = 0.f;
    for (int i = tid; i < 8192; i += NTHR) {
        s->Ahi[i] = __half(0.f);
        s->Alo[i] = __half(0.f);
    }
    float fa0[4], fa1[4];
#pragma unroll
    for (int nb = 0; nb < 4; ++nb) {
        int col = gq*32 + nb*8 + t4*2;
        fa0[nb] = Fa[(size_t)d*NH + col];
        fa1[nb] = Fa[(size_t)d*NH + col + 1];
    }
    float c[16], h2[16], num[16];
#pragma unroll
    for (int i = 0; i < 16; ++i) { c[i] = 0.f; num[i] = 0.f; }
    cp_wait<0>();
    __syncthreads();

    for (int t = 0; t < NT; ++t) {
        if (tid < BC) s->xs[tid] = x[((size_t)(b0 + tid)*NT + t)*ND + d];

        cell_hmma(wresB, aHiB, aLoB, s->ub, s->xs, lane, w, c, h2);

        // ---- epilogue ----
        {
            size_t o0 = O_OFS + (((size_t)(b0 + R)*NT + t)*ND + d)*NH;
            size_t o1 = O_OFS + (((size_t)(b0 + R + 8)*NT + t)*ND + d)*NH;
            char* ahp = (char*)s->Ahi; char* alp = (char*)s->Alo;
            float p0 = 0.f, p1 = 0.f;
#pragma unroll
            for (int nb = 0; nb < 4; ++nb) {
                int col = gq*32 + nb*8 + t4*2;
                float h00 = h2[nb*4+0], h01 = h2[nb*4+1];
                float h10 = h2[nb*4+2], h11 = h2[nb*4+3];
                *(float2*)(out + o0 + col) = make_float2(h00, h01);
                *(float2*)(out + o1 + col) = make_float2(h10, h11);
                p0 = fmaf(h00, fa0[nb], fmaf(h01, fa1[nb], p0));
                p1 = fmaf(h10, fa0[nb], fmaf(h11, fa1[nb], p1));
                unsigned sw0 = (unsigned)(R*256 + (((col>>3) ^ (R & 7)) << 4) + t4*4);
                unsigned sw1 = (unsigned)((R+8)*256 + (((col>>3) ^ ((R+8) & 7)) << 4) + t4*4);
                unsigned hv, lv;
                splitf16(h00, h01, hv, lv);
                *(unsigned*)(ahp + sw0) = hv; *(unsigned*)(alp + sw0) = lv;
                splitf16(h10, h11, hv, lv);
                *(unsigned*)(ahp + sw1) = hv; *(unsigned*)(alp + sw1) = lv;
            }
            p0 += __shfl_xor_sync(0xffffffffu, p0, 1);
            p0 += __shfl_xor_sync(0xffffffffu, p0, 2);
            p1 += __shfl_xor_sync(0xffffffffu, p1, 1);
            p1 += __shfl_xor_sync(0xffffffffu, p1, 2);
            if (t4 == 0) { s->part[R*5 + gq] = p0; s->part[(R+8)*5 + gq] = p1; }
        }
        __syncthreads();
        if (tid < 256) {
            int r2 = tid >> 2, q = tid & 3;
            float v = s->part[r2*5 + q];
            v += __shfl_xor_sync(0xffffffffu, v, 1);
            v += __shfl_xor_sync(0xffffffffu, v, 2);
            if (q == 0) {
                float e = __expf(tanha(v + fab));
                s->es[r2] = e;
                s->den_s[r2] += e;
                out[A_OFS + ((size_t)(b0 + r2)*NT + t)*ND + d] = e;
            }
        }
        __syncthreads();
        {
            float e0 = s->es[R], e1 = s->es[R + 8];
#pragma unroll
            for (int nb = 0; nb < 4; ++nb) {
                num[nb*4+0] = fmaf(e0, h2[nb*4+0], num[nb*4+0]);
                num[nb*4+1] = fmaf(e0, h2[nb*4+1], num[nb*4+1]);
                num[nb*4+2] = fmaf(e1, h2[nb*4+2], num[nb*4+2]);
                num[nb*4+3] = fmaf(e1, h2[nb*4+3], num[nb*4+3]);
            }
        }
    }

    // ---- handoff (gs staged in Wres region) ----
    float* gs = (float*)s->Wres;
    {
        float inv0 = __fdividef(1.f, s->den_s[R]);
        float inv1 = __fdividef(1.f, s->den_s[R + 8]);
        size_t g0o = ((size_t)d*NB + b0 + R)*NH;
        size_t g1o = ((size_t)d*NB + b0 + R + 8)*NH;
#pragma unroll
        for (int nb = 0; nb < 4; ++nb) {
            int col = gq*32 + nb*8 + t4*2;
            *(float2*)(g_h + g0o + col) = make_float2(h2[nb*4+0], h2[nb*4+1]);
            *(float2*)(g_h + g1o + col) = make_float2(h2[nb*4+2], h2[nb*4+3]);
            *(float2*)(g_c + g0o + col) = make_float2(c[nb*4+0], c[nb*4+1]);
            *(float2*)(g_c + g1o + col) = make_float2(c[nb*4+2], c[nb*4+3]);
            gs[R*GST + col]         = num[nb*4+0]*inv0;
            gs[R*GST + col + 1]     = num[nb*4+1]*inv0;
            gs[(R+8)*GST + col]     = num[nb*4+2]*inv1;
            gs[(R+8)*GST + col + 1] = num[nb*4+3]*inv1;
        }
    }
    if (tid < BC) g_den[(size_t)(b0 + tid)*ND + d] = s->den_s[tid];
    __syncthreads();
    {   // mu_g
        int outc = tid & 31, bg = tid >> 5;
        float a4[4];
        float pb = Phi_b[outc];
#pragma unroll
        for (int r = 0; r < 4; ++r) a4[r] = pb;
#pragma unroll 2
        for (int k = 0; k < NH; ++k) {
            float pg = Phi_w[k*NOUT + outc];
#pragma unroll
            for (int r = 0; r < 4; ++r)
                a4[r] = fmaf(gs[(bg*4 + r)*GST + k], pg, a4[r]);
        }
#pragma unroll
        for (int r = 0; r < 4; ++r)
            g_mug[(((size_t)(b0 + bg*4 + r))*ND + d)*NOUT + outc] = a4[r];
    }
    {   // bt_g
        int b = tid >> 3, seg = tid & 7;
        float a = 0.f;
#pragma unroll
        for (int kk = 0; kk < 16; ++kk) {
            int k = seg*16 + kk;
            a = fmaf(gs[b*GST + k], Fbw[k], a);
        }
        a += __shfl_xor_sync(0xffffffffu, a, 1);
        a += __shfl_xor_sync(0xffffffffu, a, 2);
        a += __shfl_xor_sync(0xffffffffu, a, 4);
        if (seg == 0) g_btg[(size_t)(b0 + b)*ND + d] = a;
    }
}

// ==== alphas finalize ====
__global__ void alphas_fin_kernel(float* __restrict__ out) {
    int i = blockIdx.x*256 + threadIdx.x;
    if (i >= A_CNT) return;
    int b = i / (NT*ND), d = i & (ND-1);
    out[A_OFS + i] = __fdividef(out[A_OFS + i], g_den[(size_t)b*ND + d]);
}

// ==== persistent forecast with resident-W HMMA cell ====
struct SFc {
    __half Wres[4*16384];         // 128KB resident
    __half Ahi[8192], Alo[8192];
    float hs[BC*GST];             // h in float for mu/bt dots
    float phi_s[NH*NOUT];
    float fbw_s[NH];
    float ub[1024];
    float xs[BC];
};

__device__ __forceinline__ void grid_bar() {
    __syncthreads();
    if (threadIdx.x == 0) {
        __threadfence();
        unsigned gen = *(volatile unsigned*)&g_gen;
        if (atomicAdd(&g_cnt, 1u) == NCTA - 1u) {
            g_cnt = 0u; __threadfence(); atomicAdd(&g_gen, 1u);
        } else {
            while (*(volatile unsigned*)&g_gen == gen) __nanosleep(64);
        }
        __threadfence();
    }
    __syncthreads();
}

__global__ void __launch_bounds__(NTHR, 1) fc_kernel(
    const float* __restrict__ Uj, const float* __restrict__ Ui,
    const float* __restrict__ Uf, const float* __restrict__ Uo,
    const float* __restrict__ bj, const float* __restrict__ bi_,
    const float* __restrict__ bf, const float* __restrict__ bo,
    const float* __restrict__ Phi_w, const float* __restrict__ Fbw,
    const float* __restrict__ Fbb,
    const float* __restrict__ proj_w, const float* __restrict__ proj_b,
    float* __restrict__ out)
{
    extern __shared__ char smraw[];
    SFc* s = (SFc*)smraw;
    const int tid = threadIdx.x;
    const int d = blockIdx.x >> 2;
    const int b0 = (blockIdx.x & 3)*BC;
    const int lane = tid & 31, w = tid >> 5;
    const int rg = w & 3, gq = w >> 2;
    const int t4 = lane & 3;
    const int R = rg*16 + (lane >> 2);
    const int outc = tid & 31, bg = tid >> 5;
    const int bb_ = tid >> 3, seg = tid & 7;
    unsigned aHiB = sptr(s->Ahi), aLoB = sptr(s->Alo), wresB = sptr(s->Wres);

    loadWres(wresB, d, tid);
    STAGE_UB(s->ub);
    for (int i = tid; i < NH*NOUT; i += NTHR)
        s->phi_s[i] = Phi_w[(NH + (i >> 5))*NOUT + (i & 31)];
    if (tid < NH) s->fbw_s[tid] = Fbw[NH + tid];

    // load h into hs + A tiles
    for (int i = tid; i < BC*64; i += NTHR) {
        int b = i >> 6, kp = (i & 63)*2;
        size_t go = ((size_t)d*NB + b0 + b)*NH + kp;
        float h0v = g_h[go], h1v = g_h[go + 1];
        s->hs[b*GST + kp] = h0v;
        s->hs[b*GST + kp + 1] = h1v;
        unsigned hv, lv;
        splitf16(h0v, h1v, hv, lv);
        unsigned sw = (unsigned)(b*256 + (((kp>>3) ^ (b & 7)) << 4) + (kp & 7)*2);
        *(unsigned*)((char*)s->Ahi + sw) = hv;
        *(unsigned*)((char*)s->Alo + sw) = lv;
    }

    float c[16], h2[16];
    {
        size_t g0o = ((size_t)d*NB + b0 + R)*NH;
        size_t g1o = ((size_t)d*NB + b0 + R + 8)*NH;
#pragma unroll
        for (int nb = 0; nb < 4; ++nb) {
            int col = gq*32 + nb*8 + t4*2;
            float2 c0v = *(const float2*)(g_c + g0o + col);
            float2 c1v = *(const float2*)(g_c + g1o + col);
            c[nb*4+0] = c0v.x; c[nb*4+1] = c0v.y;
            c[nb*4+2] = c1v.x; c[nb*4+3] = c1v.y;
        }
    }
    float mug[4];
#pragma unroll
    for (int r = 0; r < 4; ++r)
        mug[r] = g_mug[(((size_t)(b0 + bg*4 + r))*ND + d)*NOUT + outc];
    const float btg = g_btg[(size_t)(b0 + bb_)*ND + d] + Fbb[0];
    cp_wait<0>();
    __syncthreads();

    for (int f = 0; f < NF; ++f) {
        const int p = f & 1;
        {   // mu = mu_g + h . Phi_bot
            float a4[4];
#pragma unroll
            for (int r = 0; r < 4; ++r) a4[r] = mug[r];
#pragma unroll 2
            for (int k = 0; k < NH; ++k) {
                float phv = s->phi_s[k*NOUT + outc];
#pragma unroll
                for (int r = 0; r < 4; ++r)
                    a4[r] = fmaf(s->hs[(bg*4 + r)*GST + k], phv, a4[r]);
            }
#pragma unroll
            for (int r = 0; r < 4; ++r)
                g_mu2[p][(((size_t)(b0 + bg*4 + r))*ND + d)*NOUT + outc] = a4[r];
        }
        {   // bt
            float a = 0.f;
#pragma unroll
            for (int kk = 0; kk < 16; ++kk) {
                int k = seg*16 + kk;
                a = fmaf(s->hs[bb_*GST + k], s->fbw_s[k], a);
            }
            a += __shfl_xor_sync(0xffffffffu, a, 1);
            a += __shfl_xor_sync(0xffffffffu, a, 2);
            a += __shfl_xor_sync(0xffffffffu, a, 4);
            if (seg == 0)
                g_bt2[p][(size_t)(b0 + bb_)*ND + d] = __expf(tanha(a + btg));
        }
        __threadfence();
        grid_bar();

        // reduce over D: betas, y, prev -> xs
#pragma unroll
        for (int rr = 0; rr < 4; ++rr) {
            int b = w*4 + rr;
            float bt = g_bt2[p][(size_t)(b0 + b)*ND + lane];
            float ssum = bt;
#pragma unroll
            for (int o = 16; o > 0; o >>= 1)
                ssum += __shfl_xor_sync(0xffffffffu, ssum, o);
            float beta = __fdividef(bt, ssum);
            if (d == 0)
                out[B_OFS + ((size_t)(b0 + b)*NF + f)*ND + lane] = beta;
            float y = 0.f;
            const float* mup = g_mu2[p] + ((size_t)(b0 + b)*ND)*NOUT + lane;
#pragma unroll
            for (int d2 = 0; d2 < ND; ++d2)
                y = fmaf(__shfl_sync(0xffffffffu, beta, d2), mup[d2*NOUT], y);
            if (d == 0)
                out[((size_t)(b0 + b)*NF + f)*NOUT + lane] = y;
            float pr = y * proj_w[lane*ND + d];
#pragma unroll
            for (int o = 16; o > 0; o >>= 1)
                pr += __shfl_xor_sync(0xffffffffu, pr, o);
            if (lane == 0) s->xs[b] = pr + proj_b[d];
        }
        if (f == NF - 1) break;

        cell_hmma(wresB, aHiB, aLoB, s->ub, s->xs, lane, w, c, h2);

        {   // write new h -> hs + A tiles
            char* ahp = (char*)s->Ahi; char* alp = (char*)s->Alo;
#pragma unroll
            for (int nb = 0; nb < 4; ++nb) {
                int col = gq*32 + nb*8 + t4*2;
                float h00 = h2[nb*4+0], h01 = h2[nb*4+1];
                float h10 = h2[nb*4+2], h11 = h2[nb*4+3];
                s->hs[R*GST + col] = h00; s->hs[R*GST + col + 1] = h01;
                s->hs[(R+8)*GST + col] = h10; s->hs[(R+8)*GST + col + 1] = h11;
                unsigned sw0 = (unsigned)(R*256 + (((col>>3) ^ (R & 7)) << 4) + t4*4);
                unsigned sw1 = (unsigned)((R+8)*256 + (((col>>3) ^ ((R+8) & 7)) << 4) + t4*4);
                unsigned hv, lv;
                splitf16(h00, h01, hv, lv);
                *(unsigned*)(ahp + sw0) = hv; *(unsigned*)(alp + sw0) = lv;
                splitf16(h10, h11, hv, lv);
                *(unsigned*)(ahp + sw1) = hv; *(unsigned*)(alp + sw1) = lv;
            }
        }
        __syncthreads();
    }
}

// ==== launch ====
extern "C" void kernel_launch(void* const* d_in, const int* in_sizes, int n_in,
                              void* d_out, int out_size) {
    const float* x   = (const float*)d_in[0];
    const float* Uj  = (const float*)d_in[1];
    const float* Ui  = (const float*)d_in[2];
    const float* Uf  = (const float*)d_in[3];
    const float* Uo  = (const float*)d_in[4];
    const float* Wj  = (const float*)d_in[5];
    const float* Wi  = (const float*)d_in[6];
    const float* Wf  = (const float*)d_in[7];
    const float* Wo  = (const float*)d_in[8];
    const float* bj  = (const float*)d_in[9];
    const float* bi  = (const float*)d_in[10];
    const float* bf  = (const float*)d_in[11];
    const float* bo  = (const float*)d_in[12];
    const float* Fa  = (const float*)d_in[13];
    const float* Fab = (const float*)d_in[14];
    const float* Fbw = (const float*)d_in[15];
    const float* Fbb = (const float*)d_in[16];
    const float* Phw = (const float*)d_in[17];
    const float* Phb = (const float*)d_in[18];
    const float* prw = (const float*)d_in[19];
    const float* prb = (const float*)d_in[20];
    float* out = (float*)d_out;

    int smE = (int)sizeof(SEnc);
    int smF = (int)sizeof(SFc);
    cudaFuncSetAttribute(enc_kernel, cudaFuncAttributeMaxDynamicSharedMemorySize, smE);
    cudaFuncSetAttribute(fc_kernel,  cudaFuncAttributeMaxDynamicSharedMemorySize, smF);

    prep_kernel<<<4096, 256>>>(Wj, Wi, Wf, Wo);
    enc_kernel<<<NCTA, NTHR, smE>>>(x, Uj,Ui,Uf,Uo, bj,bi,bf,bo,
                                    Fa, Fab, Phw, Phb, Fbw, out);
    alphas_fin_kernel<<<(A_CNT + 255)/256, 256>>>(out);
    fc_kernel<<<NCTA, NTHR, smF>>>(Uj,Ui,Uf,Uo, bj,bi,bf,bo,
                                   Phw, Fbw, Fbb, prw, prb, out);
}